// round 10
// baseline (speedup 1.0000x reference)
#include <cuda_runtime.h>
#include <math.h>

#define SS 64
#define BB 32
#define HH 512
#define EE 512
#define VV 32000
#define LL 2
#define SB (SS*BB)   // 2048
#define HSTRIDE 520  // 512 + 8 pad

// -------- scratch (no allocation allowed; device globals instead) --------
__device__ float g_x[SB*HH];
__device__ float g_y[SB*HH];
__device__ float g_gates[3*SB*HH];

// per-bg barrier cells, each on its own 256B line (zero-init; each scan
// launch performs 64 flips per cell -> returns to 0, graph-replay safe)
struct __align__(256) BarCell { unsigned v; unsigned pad[63]; };
__device__ BarCell g_cnt2[4];
__device__ BarCell g_sense2[4];

// ---------------------------- embedding ---------------------------------
__global__ void embed_kernel(const int* __restrict__ inputs,
                             const float* __restrict__ emb,
                             float* __restrict__ out)
{
    int row = blockIdx.x;
    int tok = inputs[row];
    const float4* src = (const float4*)(emb + (size_t)tok * EE);
    float4* dst = (float4*)(out + (size_t)row * EE);
    dst[threadIdx.x] = src[threadIdx.x];
}

// ------------- tf32 tensor-core GEMM (R7 known-good config) --------------
// Block tile 128x128, BK=16, 4 warps of 64x64, 128 threads.
__device__ __forceinline__ unsigned f2tf(float x)
{
    unsigned r;
    asm("cvt.rna.tf32.f32 %0, %1;" : "=r"(r) : "f"(x));
    return r;
}

__device__ __forceinline__ void gemm_tf32_body(
    unsigned* __restrict__ As, unsigned* __restrict__ Bs,   // each 2*128*16
    const float* __restrict__ A, const float* __restrict__ W,
    const float* __restrict__ bias, float* __restrict__ C,
    int M, int N, int K)
{
    const int tid  = threadIdx.x;
    const int lane = tid & 31;
    const int warp = tid >> 5;
    const int wm = (warp >> 1) * 64;
    const int wn = (warp & 1) * 64;
    const int m0 = blockIdx.y * 128;
    const int n0 = blockIdx.x * 128;
    const int fr = lane >> 2;
    const int fc = lane & 3;
    const int cm  = tid >> 2;
    const int cc2 = tid & 3;

    float acc[4][8][4];
#pragma unroll
    for (int mt = 0; mt < 4; ++mt)
#pragma unroll
        for (int nt = 0; nt < 8; ++nt)
#pragma unroll
            for (int q = 0; q < 4; ++q) acc[mt][nt][q] = 0.f;

    float4 ra[4], rb[4];

#define LD_STAGE(k0)                                                          \
    {                                                                         \
        _Pragma("unroll")                                                     \
        for (int i = 0; i < 4; ++i) {                                         \
            int m = i * 32 + cm;                                              \
            ra[i] = *(const float4*)&A[(size_t)(m0 + m) * K + (k0) + cc2*4];  \
            rb[i] = *(const float4*)&W[(size_t)(n0 + m) * K + (k0) + cc2*4];  \
        }                                                                     \
    }

#define ST_STAGE(buf)                                                         \
    {                                                                         \
        _Pragma("unroll")                                                     \
        for (int i = 0; i < 4; ++i) {                                         \
            int m = i * 32 + cm;                                              \
            int off = (buf) * 2048 + m * 16 + ((cc2 ^ (m & 3)) << 2);         \
            uint4 ua; ua.x = f2tf(ra[i].x); ua.y = f2tf(ra[i].y);             \
            ua.z = f2tf(ra[i].z); ua.w = f2tf(ra[i].w);                       \
            uint4 ub; ub.x = f2tf(rb[i].x); ub.y = f2tf(rb[i].y);             \
            ub.z = f2tf(rb[i].z); ub.w = f2tf(rb[i].w);                       \
            *(uint4*)&As[off] = ua;                                           \
            *(uint4*)&Bs[off] = ub;                                           \
        }                                                                     \
    }

    LD_STAGE(0);
    ST_STAGE(0);
    __syncthreads();

    const int nstages = K / 16;
    for (int s = 0; s < nstages; ++s) {
        const int buf = s & 1;
        if (s + 1 < nstages) LD_STAGE((s + 1) * 16);

#pragma unroll
        for (int k8 = 0; k8 < 2; ++k8) {
            unsigned af[4][4], bf[8][2];
#pragma unroll
            for (int mt = 0; mt < 4; ++mt) {
                int r1 = wm + mt * 16 + fr;
                int r2 = r1 + 8;
                af[mt][0] = As[buf*2048 + r1*16 + (((k8*2+0) ^ (r1&3)) << 2) + fc];
                af[mt][1] = As[buf*2048 + r2*16 + (((k8*2+0) ^ (r2&3)) << 2) + fc];
                af[mt][2] = As[buf*2048 + r1*16 + (((k8*2+1) ^ (r1&3)) << 2) + fc];
                af[mt][3] = As[buf*2048 + r2*16 + (((k8*2+1) ^ (r2&3)) << 2) + fc];
            }
#pragma unroll
            for (int nt = 0; nt < 8; ++nt) {
                int n = wn + nt * 8 + fr;
                bf[nt][0] = Bs[buf*2048 + n*16 + (((k8*2+0) ^ (n&3)) << 2) + fc];
                bf[nt][1] = Bs[buf*2048 + n*16 + (((k8*2+1) ^ (n&3)) << 2) + fc];
            }
#pragma unroll
            for (int mt = 0; mt < 4; ++mt)
#pragma unroll
                for (int nt = 0; nt < 8; ++nt) {
                    asm volatile(
                        "mma.sync.aligned.m16n8k8.row.col.f32.tf32.tf32.f32 "
                        "{%0,%1,%2,%3}, {%4,%5,%6,%7}, {%8,%9}, {%0,%1,%2,%3};"
                        : "+f"(acc[mt][nt][0]), "+f"(acc[mt][nt][1]),
                          "+f"(acc[mt][nt][2]), "+f"(acc[mt][nt][3])
                        : "r"(af[mt][0]), "r"(af[mt][1]),
                          "r"(af[mt][2]), "r"(af[mt][3]),
                          "r"(bf[nt][0]), "r"(bf[nt][1]));
                }
        }
        if (s + 1 < nstages) ST_STAGE(buf ^ 1);
        __syncthreads();
    }
#undef LD_STAGE
#undef ST_STAGE

#pragma unroll
    for (int mt = 0; mt < 4; ++mt) {
        int row = m0 + wm + mt * 16 + fr;
#pragma unroll
        for (int nt = 0; nt < 8; ++nt) {
            int col = n0 + wn + nt * 8 + fc * 2;
            float bv0 = bias[col], bv1 = bias[col + 1];
            float2 v0; v0.x = acc[mt][nt][0] + bv0; v0.y = acc[mt][nt][1] + bv1;
            float2 v1; v1.x = acc[mt][nt][2] + bv0; v1.y = acc[mt][nt][3] + bv1;
            *(float2*)&C[(size_t)row * N + col] = v0;
            *(float2*)&C[(size_t)(row + 8) * N + col] = v1;
        }
    }
}

__global__ __launch_bounds__(128) void gemm_tf32_nt_bias(
    const float* __restrict__ A, const float* __restrict__ W,
    const float* __restrict__ bias, float* __restrict__ C,
    int M, int N, int K)
{
    __shared__ unsigned As[2 * 2048];
    __shared__ unsigned Bs[2 * 2048];
    gemm_tf32_body(As, Bs, A, W, bias, C, M, N, K);
}

__global__ __launch_bounds__(128) void gemm_tf32_nt_bias3(
    const float* __restrict__ A,
    const float* __restrict__ W0, const float* __restrict__ W1, const float* __restrict__ W2,
    const float* __restrict__ b0, const float* __restrict__ b1, const float* __restrict__ b2,
    float* __restrict__ C0, float* __restrict__ C1, float* __restrict__ C2,
    int M, int N, int K)
{
    __shared__ unsigned As[2 * 2048];
    __shared__ unsigned Bs[2 * 2048];
    const float* W    = (blockIdx.z == 0) ? W0 : (blockIdx.z == 1) ? W1 : W2;
    const float* bias = (blockIdx.z == 0) ? b0 : (blockIdx.z == 1) ? b1 : b2;
    float* C          = (blockIdx.z == 0) ? C0 : (blockIdx.z == 1) ? C1 : C2;
    gemm_tf32_body(As, Bs, A, W, bias, C, M, N, K);
}

// ------------- persistent GRU scan v6: dual-bg pipelined -----------------
// 64 blocks = 32 j-groups x 2 bg-pairs. Block (jg,p) owns j in
// [16*jg, 16*jg+16) for bg0=2p and bg1=2p+1 (weights shared: same j rows).
// Per step: compute bg0 -> arrive bar0 -> compute bg1 -> arrive bar1 ->
// spin bar0 -> restage bg0 (cp.async group) -> spin bar1 -> restage bg1.
// bg1 compute hides bar0 release; bg0 restage hides bar1 wait.
__device__ __forceinline__ void fma2(unsigned long long& a,
                                     unsigned long long x, unsigned long long h)
{
    asm("fma.rn.f32x2 %0, %1, %2, %0;" : "+l"(a) : "l"(x), "l"(h));
}

__device__ __forceinline__ void bar_arrive(unsigned* cntp, unsigned* sensep,
                                           unsigned ns)
{
    unsigned old;
    asm volatile("atom.release.gpu.add.u32 %0, [%1], %2;"
                 : "=r"(old) : "l"(cntp), "r"(1u) : "memory");
    if (old == 31u) {
        asm volatile("st.relaxed.gpu.u32 [%0], %1;"
                     :: "l"(cntp), "r"(0u) : "memory");
        asm volatile("st.release.gpu.u32 [%0], %1;"
                     :: "l"(sensep), "r"(ns) : "memory");
    }
}

__device__ __forceinline__ void bar_spin(unsigned* sensep, unsigned ns)
{
    unsigned v;
    do {
        asm volatile("ld.acquire.gpu.u32 %0, [%1];"
                     : "=r"(v) : "l"(sensep) : "memory");
    } while (v != ns);
}

__global__ __launch_bounds__(512, 1) void gru_scan_kernel(
    const float* __restrict__ gates,   // [3][SB][HH]
    const float* __restrict__ Wr,
    const float* __restrict__ Wz,
    const float* __restrict__ Wh,
    const float* __restrict__ h0,      // [BB][HH]
    float* __restrict__ hs_out,        // [SS][BB][HH]
    float* __restrict__ hfin)          // [BB][HH] or null
{
    extern __shared__ float sm[];
    float* hsm0 = sm;                        // [8][HSTRIDE] bg0
    float* hsm1 = sm + 8 * HSTRIDE;          // [8][HSTRIDE] bg1
    float* red  = sm + 16 * HSTRIDE;         // [16][24][33]

    const int tid  = threadIdx.x;
    const int lane = tid & 31;
    const int w    = tid >> 5;               // 0..15
    const int bid  = blockIdx.x;
    const int jg   = bid & 31;               // 0..31
    const int p    = bid >> 5;               // 0..1
    const int bg0  = p * 2;
    const int bg1  = p * 2 + 1;
    const int j    = jg * 16 + w;

    unsigned* cnt0   = &g_cnt2[bg0].v;
    unsigned* sense0 = &g_sense2[bg0].v;
    unsigned* cnt1   = &g_cnt2[bg1].v;
    unsigned* sense1 = &g_sense2[bg1].v;

    // hoist this warp's 3 weight rows into registers (shared by both bgs)
    ulonglong2 wv[3][4];
    {
        const float* W0 = Wr + (size_t)j * HH;
        const float* W1 = Wz + (size_t)j * HH;
        const float* W2 = Wh + (size_t)j * HH;
#pragma unroll
        for (int i = 0; i < 4; ++i) {
            int kof = 4 * lane + 128 * i;
            wv[0][i] = *(const ulonglong2*)&W0[kof];
            wv[1][i] = *(const ulonglong2*)&W1[kof];
            wv[2][i] = *(const ulonglong2*)&W2[kof];
        }
    }

    const int ob  = lane & 7;                // local batch for output lanes
    const int b0  = bg0 * 8 + ob;
    const int b1  = bg1 * 8 + ob;

    // gate prefetch for step 0, both bgs
    float xr0 = 0.f, xz0 = 0.f, xh0 = 0.f;
    float xr1 = 0.f, xz1 = 0.f, xh1 = 0.f;
    if (lane < 8) {
        size_t i0 = (size_t)b0 * HH + j;
        size_t i1 = (size_t)b1 * HH + j;
        xr0 = __ldcg(&gates[i0]);
        xz0 = __ldcg(&gates[(size_t)SB * HH + i0]);
        xh0 = __ldcg(&gates[(size_t)2 * SB * HH + i0]);
        xr1 = __ldcg(&gates[i1]);
        xz1 = __ldcg(&gates[(size_t)SB * HH + i1]);
        xh1 = __ldcg(&gates[(size_t)2 * SB * HH + i1]);
    }

    // stage macro: 8 rows of src (batch base bb) into dst smem buffer
#define STAGE(dstp, src, bb)                                                  \
    {                                                                         \
        _Pragma("unroll")                                                     \
        for (int it = 0; it < 2; ++it) {                                      \
            int c = tid + it * 512;                                           \
            int bs = c >> 7;                                                  \
            int kq = c & 127;                                                 \
            unsigned da = (unsigned)__cvta_generic_to_shared(                 \
                &(dstp)[bs * HSTRIDE + kq * 4]);                              \
            const float* sa = (src) + (size_t)((bb) + bs) * HH + kq * 4;      \
            asm volatile("cp.async.cg.shared.global [%0], [%1], 16;"          \
                         :: "r"(da), "l"(sa));                                \
        }                                                                     \
        asm volatile("cp.async.commit_group;");                               \
    }

    // prologue: stage step-0 h for bg0 then bg1 (two groups pending)
    STAGE(hsm0, h0, bg0 * 8)
    STAGE(hsm1, h0, bg1 * 8)

    unsigned local_sense = 0;

    // per-bg compute macro: reads hp, uses gate regs, writes outputs
#define COMPUTE_BG(hp, XR, XZ, XH, BOUT)                                      \
    {                                                                         \
        unsigned long long acc[3][8];                                         \
        _Pragma("unroll")                                                     \
        for (int g = 0; g < 3; ++g)                                           \
            _Pragma("unroll")                                                 \
            for (int c = 0; c < 8; ++c) acc[g][c] = 0ULL;                     \
        _Pragma("unroll")                                                     \
        for (int i = 0; i < 4; ++i) {                                         \
            const int kof = 4 * lane + 128 * i;                               \
            _Pragma("unroll")                                                 \
            for (int c = 0; c < 8; ++c) {                                     \
                ulonglong2 hv = *(const ulonglong2*)&(hp)[c * HSTRIDE + kof]; \
                fma2(acc[0][c], wv[0][i].x, hv.x);                            \
                fma2(acc[0][c], wv[0][i].y, hv.y);                            \
                fma2(acc[1][c], wv[1][i].x, hv.x);                            \
                fma2(acc[1][c], wv[1][i].y, hv.y);                            \
                fma2(acc[2][c], wv[2][i].x, hv.x);                            \
                fma2(acc[2][c], wv[2][i].y, hv.y);                            \
            }                                                                 \
        }                                                                     \
        _Pragma("unroll")                                                     \
        for (int g = 0; g < 3; ++g)                                           \
            _Pragma("unroll")                                                 \
            for (int c = 0; c < 8; ++c) {                                     \
                float2 f = *(float2*)&acc[g][c];                              \
                red[(w * 24 + g * 8 + c) * 33 + lane] = f.x + f.y;            \
            }                                                                 \
        __syncwarp();                                                         \
        float sum = 0.f;                                                      \
        if (lane < 24) {                                                      \
            int base = (w * 24 + lane) * 33;                                  \
            _Pragma("unroll")                                                 \
            for (int i = 0; i < 32; ++i) sum += red[base + i];                \
        }                                                                     \
        float q0 = __shfl_sync(0xffffffffu, sum, (lane & 7));                 \
        float q1 = __shfl_sync(0xffffffffu, sum, 8 + (lane & 7));             \
        float q2 = __shfl_sync(0xffffffffu, sum, 16 + (lane & 7));            \
        if (lane < 8) {                                                       \
            float hold = (hp)[ob * HSTRIDE + j];                              \
            float r  = 1.f / (1.f + __expf(-((XR) + q0)));                    \
            float z  = 1.f / (1.f + __expf(-((XZ) + q1)));                    \
            float hc = tanhf((XH) + r * q2);                                  \
            float hn = (1.f - z) * hc + z * hold;                             \
            hdst[(size_t)(BOUT) * HH + j] = hn;                               \
            if (s == SS - 1 && hfin) hfin[(size_t)(BOUT) * HH + j] = hn;      \
        }                                                                     \
    }

    for (int s = 0; s < SS; ++s) {
        float* hdst = hs_out + (size_t)s * BB * HH;
        const float* hnext = hs_out + (size_t)s * BB * HH;  // restage source
        unsigned ns = local_sense ^ 1u;

        // ---- bg0: wait its stage, compute, arrive ----
        asm volatile("cp.async.wait_group 1;");
        __syncthreads();
        COMPUTE_BG(hsm0, xr0, xz0, xh0, b0)
        __syncthreads();
        if (tid == 0) bar_arrive(cnt0, sense0, ns);

        // ---- bg1: wait its stage, compute, arrive ----
        asm volatile("cp.async.wait_group 0;");
        __syncthreads();
        COMPUTE_BG(hsm1, xr1, xz1, xh1, b1)
        __syncthreads();
        if (tid == 0) bar_arrive(cnt1, sense1, ns);

        // ---- prefetch next gates (independent of barriers) ----
        if (lane < 8 && s + 1 < SS) {
            size_t i0 = (size_t)((s + 1) * BB + b0) * HH + j;
            size_t i1 = (size_t)((s + 1) * BB + b1) * HH + j;
            xr0 = __ldcg(&gates[i0]);
            xz0 = __ldcg(&gates[(size_t)SB * HH + i0]);
            xh0 = __ldcg(&gates[(size_t)2 * SB * HH + i0]);
            xr1 = __ldcg(&gates[i1]);
            xz1 = __ldcg(&gates[(size_t)SB * HH + i1]);
            xh1 = __ldcg(&gates[(size_t)2 * SB * HH + i1]);
        }

        // ---- restage for next step: spin bg0, stage bg0; spin bg1, stage ----
        if (s + 1 < SS) {
            if (tid == 0) bar_spin(sense0, ns);
            __syncthreads();
            STAGE(hsm0, hnext, bg0 * 8)
            if (tid == 0) bar_spin(sense1, ns);
            __syncthreads();
            STAGE(hsm1, hnext, bg1 * 8)
        }
        local_sense = ns;
    }
#undef COMPUTE_BG
#undef STAGE
}

// ------------------------------ driver ----------------------------------
extern "C" void kernel_launch(void* const* d_in, const int* in_sizes, int n_in,
                              void* d_out, int out_size)
{
    const int*   inputs = (const int*)d_in[0];
    const float* hidden = (const float*)d_in[1];
    const float* emb    = (const float*)d_in[2];
    const float* Wir    = (const float*)d_in[3];
    const float* bir    = (const float*)d_in[4];
    const float* Wiz    = (const float*)d_in[5];
    const float* biz    = (const float*)d_in[6];
    const float* Wih    = (const float*)d_in[7];
    const float* bih    = (const float*)d_in[8];
    const float* Whr    = (const float*)d_in[9];
    const float* Whz    = (const float*)d_in[10];
    const float* Whh    = (const float*)d_in[11];
    const float* Wout   = (const float*)d_in[12];
    const float* bout   = (const float*)d_in[13];
    float* out = (float*)d_out;

    float *px, *py, *pg;
    cudaGetSymbolAddress((void**)&px, g_x);
    cudaGetSymbolAddress((void**)&py, g_y);
    cudaGetSymbolAddress((void**)&pg, g_gates);

    const size_t logits_elems = (size_t)SB * VV;
    float* hfin_base = nullptr;
    if ((size_t)out_size >= logits_elems + (size_t)LL * BB * HH)
        hfin_base = out + logits_elems;

    const int smem_scan = (16 * HSTRIDE + 16 * 24 * 33) * sizeof(float);
    cudaFuncSetAttribute(gru_scan_kernel,
                         cudaFuncAttributeMaxDynamicSharedMemorySize, smem_scan);

    // 1) embedding
    embed_kernel<<<SB, 128>>>(inputs, emb, px);

    const size_t CHNK = (size_t)SB * HH;
    for (int l = 0; l < LL; ++l) {
        float* in   = (l == 0) ? px : py;
        float* outb = (l == 0) ? py : px;

        // 2) fused input projections (tf32 mma, gate = blockIdx.z)
        dim3 gProj(HH / 128, SB / 128, 3);   // (4, 16, 3)
        gemm_tf32_nt_bias3<<<gProj, 128>>>(
            in,
            Wir + (size_t)l * HH * EE, Wiz + (size_t)l * HH * EE, Wih + (size_t)l * HH * EE,
            bir + l * HH, biz + l * HH, bih + l * HH,
            pg + 0 * CHNK, pg + 1 * CHNK, pg + 2 * CHNK,
            SB, HH, EE);

        // 3) persistent dual-bg pipelined scan (64 blocks)
        gru_scan_kernel<<<64, 512, smem_scan>>>(
            pg,
            Whr + (size_t)l * HH * HH,
            Whz + (size_t)l * HH * HH,
            Whh + (size_t)l * HH * HH,
            hidden + (size_t)l * BB * HH,
            outb,
            hfin_base ? hfin_base + (size_t)l * BB * HH : nullptr);
    }

    // 4) logits GEMM via tf32 tensor cores (128x128 tiles, 4 warps)
    dim3 gLog(VV / 128, SB / 128);   // (250, 16)
    gemm_tf32_nt_bias<<<gLog, 128>>>(px, Wout, bout, out, SB, VV, EE);
}

// round 11
// speedup vs baseline: 1.2816x; 1.2816x over previous
#include <cuda_runtime.h>
#include <math.h>

#define SS 64
#define BB 32
#define HH 512
#define EE 512
#define VV 32000
#define LL 2
#define SB (SS*BB)   // 2048
#define NBLK 128

// -------- scratch (no allocation allowed; device globals instead) --------
__device__ float g_x[SB*HH];
__device__ float g_y[SB*HH];
__device__ float g_gates[3*SB*HH];

// per-bg barrier cells, each on its own 256B line (zero-init; each scan
// launch performs 64 flips per cell -> returns to 0, graph-replay safe)
struct __align__(256) BarCell { unsigned v; unsigned pad[63]; };
__device__ BarCell g_cnt2[4];
__device__ BarCell g_sense2[4];

// ---------------------------- embedding ---------------------------------
__global__ void embed_kernel(const int* __restrict__ inputs,
                             const float* __restrict__ emb,
                             float* __restrict__ out)
{
    int row = blockIdx.x;
    int tok = inputs[row];
    const float4* src = (const float4*)(emb + (size_t)tok * EE);
    float4* dst = (float4*)(out + (size_t)row * EE);
    dst[threadIdx.x] = src[threadIdx.x];
}

// ------------- tf32 tensor-core GEMM (R7 known-good config) --------------
// Block tile 128x128, BK=16, 4 warps of 64x64, 128 threads.
__device__ __forceinline__ unsigned f2tf(float x)
{
    unsigned r;
    asm("cvt.rna.tf32.f32 %0, %1;" : "=r"(r) : "f"(x));
    return r;
}

__device__ __forceinline__ void gemm_tf32_body(
    unsigned* __restrict__ As, unsigned* __restrict__ Bs,   // each 2*128*16
    const float* __restrict__ A, const float* __restrict__ W,
    const float* __restrict__ bias, float* __restrict__ C,
    int M, int N, int K)
{
    const int tid  = threadIdx.x;
    const int lane = tid & 31;
    const int warp = tid >> 5;
    const int wm = (warp >> 1) * 64;
    const int wn = (warp & 1) * 64;
    const int m0 = blockIdx.y * 128;
    const int n0 = blockIdx.x * 128;
    const int fr = lane >> 2;
    const int fc = lane & 3;
    const int cm  = tid >> 2;
    const int cc2 = tid & 3;

    float acc[4][8][4];
#pragma unroll
    for (int mt = 0; mt < 4; ++mt)
#pragma unroll
        for (int nt = 0; nt < 8; ++nt)
#pragma unroll
            for (int q = 0; q < 4; ++q) acc[mt][nt][q] = 0.f;

    float4 ra[4], rb[4];

#define LD_STAGE(k0)                                                          \
    {                                                                         \
        _Pragma("unroll")                                                     \
        for (int i = 0; i < 4; ++i) {                                         \
            int m = i * 32 + cm;                                              \
            ra[i] = *(const float4*)&A[(size_t)(m0 + m) * K + (k0) + cc2*4];  \
            rb[i] = *(const float4*)&W[(size_t)(n0 + m) * K + (k0) + cc2*4];  \
        }                                                                     \
    }

#define ST_STAGE(buf)                                                         \
    {                                                                         \
        _Pragma("unroll")                                                     \
        for (int i = 0; i < 4; ++i) {                                         \
            int m = i * 32 + cm;                                              \
            int off = (buf) * 2048 + m * 16 + ((cc2 ^ (m & 3)) << 2);         \
            uint4 ua; ua.x = f2tf(ra[i].x); ua.y = f2tf(ra[i].y);             \
            ua.z = f2tf(ra[i].z); ua.w = f2tf(ra[i].w);                       \
            uint4 ub; ub.x = f2tf(rb[i].x); ub.y = f2tf(rb[i].y);             \
            ub.z = f2tf(rb[i].z); ub.w = f2tf(rb[i].w);                       \
            *(uint4*)&As[off] = ua;                                           \
            *(uint4*)&Bs[off] = ub;                                           \
        }                                                                     \
    }

    LD_STAGE(0);
    ST_STAGE(0);
    __syncthreads();

    const int nstages = K / 16;
    for (int s = 0; s < nstages; ++s) {
        const int buf = s & 1;
        if (s + 1 < nstages) LD_STAGE((s + 1) * 16);

#pragma unroll
        for (int k8 = 0; k8 < 2; ++k8) {
            unsigned af[4][4], bf[8][2];
#pragma unroll
            for (int mt = 0; mt < 4; ++mt) {
                int r1 = wm + mt * 16 + fr;
                int r2 = r1 + 8;
                af[mt][0] = As[buf*2048 + r1*16 + (((k8*2+0) ^ (r1&3)) << 2) + fc];
                af[mt][1] = As[buf*2048 + r2*16 + (((k8*2+0) ^ (r2&3)) << 2) + fc];
                af[mt][2] = As[buf*2048 + r1*16 + (((k8*2+1) ^ (r1&3)) << 2) + fc];
                af[mt][3] = As[buf*2048 + r2*16 + (((k8*2+1) ^ (r2&3)) << 2) + fc];
            }
#pragma unroll
            for (int nt = 0; nt < 8; ++nt) {
                int n = wn + nt * 8 + fr;
                bf[nt][0] = Bs[buf*2048 + n*16 + (((k8*2+0) ^ (n&3)) << 2) + fc];
                bf[nt][1] = Bs[buf*2048 + n*16 + (((k8*2+1) ^ (n&3)) << 2) + fc];
            }
#pragma unroll
            for (int mt = 0; mt < 4; ++mt)
#pragma unroll
                for (int nt = 0; nt < 8; ++nt) {
                    asm volatile(
                        "mma.sync.aligned.m16n8k8.row.col.f32.tf32.tf32.f32 "
                        "{%0,%1,%2,%3}, {%4,%5,%6,%7}, {%8,%9}, {%0,%1,%2,%3};"
                        : "+f"(acc[mt][nt][0]), "+f"(acc[mt][nt][1]),
                          "+f"(acc[mt][nt][2]), "+f"(acc[mt][nt][3])
                        : "r"(af[mt][0]), "r"(af[mt][1]),
                          "r"(af[mt][2]), "r"(af[mt][3]),
                          "r"(bf[nt][0]), "r"(bf[nt][1]));
                }
        }
        if (s + 1 < nstages) ST_STAGE(buf ^ 1);
        __syncthreads();
    }
#undef LD_STAGE
#undef ST_STAGE

#pragma unroll
    for (int mt = 0; mt < 4; ++mt) {
        int row = m0 + wm + mt * 16 + fr;
#pragma unroll
        for (int nt = 0; nt < 8; ++nt) {
            int col = n0 + wn + nt * 8 + fc * 2;
            float bv0 = bias[col], bv1 = bias[col + 1];
            float2 v0; v0.x = acc[mt][nt][0] + bv0; v0.y = acc[mt][nt][1] + bv1;
            float2 v1; v1.x = acc[mt][nt][2] + bv0; v1.y = acc[mt][nt][3] + bv1;
            *(float2*)&C[(size_t)row * N + col] = v0;
            *(float2*)&C[(size_t)(row + 8) * N + col] = v1;
        }
    }
}

__global__ __launch_bounds__(128) void gemm_tf32_nt_bias(
    const float* __restrict__ A, const float* __restrict__ W,
    const float* __restrict__ bias, float* __restrict__ C,
    int M, int N, int K)
{
    __shared__ unsigned As[2 * 2048];
    __shared__ unsigned Bs[2 * 2048];
    gemm_tf32_body(As, Bs, A, W, bias, C, M, N, K);
}

__global__ __launch_bounds__(128) void gemm_tf32_nt_bias3(
    const float* __restrict__ A,
    const float* __restrict__ W0, const float* __restrict__ W1, const float* __restrict__ W2,
    const float* __restrict__ b0, const float* __restrict__ b1, const float* __restrict__ b2,
    float* __restrict__ C0, float* __restrict__ C1, float* __restrict__ C2,
    int M, int N, int K)
{
    __shared__ unsigned As[2 * 2048];
    __shared__ unsigned Bs[2 * 2048];
    const float* W    = (blockIdx.z == 0) ? W0 : (blockIdx.z == 1) ? W1 : W2;
    const float* bias = (blockIdx.z == 0) ? b0 : (blockIdx.z == 1) ? b1 : b2;
    float* C          = (blockIdx.z == 0) ? C0 : (blockIdx.z == 1) ? C1 : C2;
    gemm_tf32_body(As, Bs, A, W, bias, C, M, N, K);
}

// ------------- persistent GRU scan v7: R7 + bulk-copy staging ------------
// 128 blocks = 32 j-groups x 4 b-groups, per-bg split barriers (R7).
// h staging = ONE cp.async.bulk (UBLKCP) of 16KB per block per step,
// completion via mbarrier parity — removes ~2000 issue-cycles/step of
// per-thread cp.async. No smem row padding (compute access is row-major
// contiguous LDS.128 -> conflict-free without it).
__device__ __forceinline__ void fma2(unsigned long long& a,
                                     unsigned long long x, unsigned long long h)
{
    asm("fma.rn.f32x2 %0, %1, %2, %0;" : "+l"(a) : "l"(x), "l"(h));
}

__device__ __forceinline__ unsigned smem_u32(const void* p)
{
    unsigned a;
    asm("{ .reg .u64 t; cvta.to.shared.u64 t, %1; cvt.u32.u64 %0, t; }"
        : "=r"(a) : "l"(p));
    return a;
}

__global__ __launch_bounds__(512, 1) void gru_scan_kernel(
    const float* __restrict__ gates,   // [3][SB][HH]
    const float* __restrict__ Wr,
    const float* __restrict__ Wz,
    const float* __restrict__ Wh,
    const float* __restrict__ h0,      // [BB][HH]
    float* __restrict__ hs_out,        // [SS][BB][HH]
    float* __restrict__ hfin)          // [BB][HH] or null
{
    extern __shared__ float sm[];
    float* hsm = sm;                       // [8][512] = 16KB, no pad
    float* red = sm + 8 * 512;             // [16][24][33]
    unsigned mbar = smem_u32(sm + 8 * 512 + 16 * 24 * 33);  // 8B mbarrier

    const int tid  = threadIdx.x;
    const int lane = tid & 31;
    const int w    = tid >> 5;             // 0..15 = jl
    const int bid  = blockIdx.x;
    const int jg   = bid >> 2;             // 0..31
    const int bg   = bid & 3;              // 0..3
    const int j    = jg * 16 + w;

    unsigned* cntp   = &g_cnt2[bg].v;
    unsigned* sensep = &g_sense2[bg].v;

    // hoist this warp's 3 weight rows into registers
    ulonglong2 wv[3][4];
    {
        const float* W0 = Wr + (size_t)j * HH;
        const float* W1 = Wz + (size_t)j * HH;
        const float* W2 = Wh + (size_t)j * HH;
#pragma unroll
        for (int i = 0; i < 4; ++i) {
            int kof = 4 * lane + 128 * i;
            wv[0][i] = *(const ulonglong2*)&W0[kof];
            wv[1][i] = *(const ulonglong2*)&W1[kof];
            wv[2][i] = *(const ulonglong2*)&W2[kof];
        }
    }

    const int b = bg * 8 + (lane & 7);     // output batch for lanes<8

    float xr = 0.f, xz = 0.f, xh = 0.f;
    if (lane < 8) {
        size_t idx = (size_t)(0 * BB + b) * HH + j;
        xr = __ldcg(&gates[idx]);
        xz = __ldcg(&gates[(size_t)SB * HH + idx]);
        xh = __ldcg(&gates[(size_t)2 * SB * HH + idx]);
    }

    // ---- mbarrier init + prologue bulk stage (step 0 from h0) ----
    if (tid == 0) {
        asm volatile("mbarrier.init.shared.b64 [%0], %1;"
                     :: "r"(mbar), "r"(1u) : "memory");
    }
    __syncthreads();
    if (tid == 0) {
        asm volatile("mbarrier.arrive.expect_tx.shared.b64 _, [%0], %1;"
                     :: "r"(mbar), "r"(16384u) : "memory");
        asm volatile(
            "cp.async.bulk.shared::cluster.global.mbarrier::complete_tx::bytes "
            "[%0], [%1], %2, [%3];"
            :: "r"(smem_u32(hsm)), "l"(h0 + (size_t)(bg * 8) * HH),
               "r"(16384u), "r"(mbar) : "memory");
    }

    unsigned local_sense = 0;

    for (int s = 0; s < SS; ++s) {
        float* hdst = hs_out + (size_t)s * BB * HH;

        // ---- wait for this step's bulk stage ----
        {
            unsigned phase = (unsigned)(s & 1);
            unsigned done;
            asm volatile(
                "{ .reg .pred p;\n\t"
                "mbarrier.try_wait.parity.acquire.cta.shared::cta.b64 p, [%1], %2;\n\t"
                "selp.b32 %0, 1, 0, p; }"
                : "=r"(done) : "r"(mbar), "r"(phase) : "memory");
            if (!done) {
                asm volatile(
                    "{ .reg .pred P1;\n\t"
                    "WAIT_LOOP_%=:\n\t"
                    "mbarrier.try_wait.parity.acquire.cta.shared::cta.b64 P1, [%0], %1, 0x989680;\n\t"
                    "@P1 bra.uni WAIT_DONE_%=;\n\t"
                    "bra.uni WAIT_LOOP_%=;\n\t"
                    "WAIT_DONE_%=:\n\t"
                    "}"
                    :: "r"(mbar), "r"(phase) : "memory");
            }
        }

        // ---- dot products: 3 gates x 8 b, k split over 32 lanes x 16 ----
        unsigned long long acc[3][8];
#pragma unroll
        for (int g = 0; g < 3; ++g)
#pragma unroll
            for (int c = 0; c < 8; ++c) acc[g][c] = 0ULL;

#pragma unroll
        for (int i = 0; i < 4; ++i) {
            const int kof = 4 * lane + 128 * i;
#pragma unroll
            for (int c = 0; c < 8; ++c) {
                ulonglong2 hv = *(const ulonglong2*)&hsm[c * 512 + kof];
                fma2(acc[0][c], wv[0][i].x, hv.x);
                fma2(acc[0][c], wv[0][i].y, hv.y);
                fma2(acc[1][c], wv[1][i].x, hv.x);
                fma2(acc[1][c], wv[1][i].y, hv.y);
                fma2(acc[2][c], wv[2][i].x, hv.x);
                fma2(acc[2][c], wv[2][i].y, hv.y);
            }
        }

#pragma unroll
        for (int g = 0; g < 3; ++g)
#pragma unroll
            for (int c = 0; c < 8; ++c) {
                float2 f = *(float2*)&acc[g][c];
                red[(w * 24 + g * 8 + c) * 33 + lane] = f.x + f.y;
            }
        __syncwarp();

        float sum = 0.f;
        if (lane < 24) {
            int base = (w * 24 + lane) * 33;
#pragma unroll
            for (int i = 0; i < 32; ++i) sum += red[base + i];
        }
        float s0 = __shfl_sync(0xffffffffu, sum, (lane & 7));
        float s1 = __shfl_sync(0xffffffffu, sum, 8 + (lane & 7));
        float s2 = __shfl_sync(0xffffffffu, sum, 16 + (lane & 7));

        if (lane < 8) {
            float hold = hsm[(lane & 7) * 512 + j];
            float r  = 1.f / (1.f + __expf(-(xr + s0)));
            float z  = 1.f / (1.f + __expf(-(xz + s1)));
            float hc = tanhf(xh + r * s2);
            float hn = (1.f - z) * hc + z * hold;
            hdst[(size_t)b * HH + j] = hn;
            if (s == SS - 1 && hfin) hfin[(size_t)b * HH + j] = hn;
        }

        if (lane < 8 && s + 1 < SS) {
            size_t idx = (size_t)((s + 1) * BB + b) * HH + j;
            xr = __ldcg(&gates[idx]);
            xz = __ldcg(&gates[(size_t)SB * HH + idx]);
            xh = __ldcg(&gates[(size_t)2 * SB * HH + idx]);
        }

        // ---- per-bg grid barrier (R7) ----
        __syncthreads();
        if (tid == 0) {
            unsigned ns = local_sense ^ 1u;
            unsigned old;
            asm volatile("atom.release.gpu.add.u32 %0, [%1], %2;"
                         : "=r"(old) : "l"(cntp), "r"(1u) : "memory");
            if (old == 31u) {
                asm volatile("st.relaxed.gpu.u32 [%0], %1;"
                             :: "l"(cntp), "r"(0u) : "memory");
                asm volatile("st.release.gpu.u32 [%0], %1;"
                             :: "l"(sensep), "r"(ns) : "memory");
            } else {
                unsigned v;
                do {
                    asm volatile("ld.acquire.gpu.u32 %0, [%1];"
                                 : "=r"(v) : "l"(sensep) : "memory");
                } while (v != ns);
            }
        }
        local_sense ^= 1u;
        __syncthreads();

        // ---- issue next step's bulk stage (h(s) now globally visible) ----
        if (s + 1 < SS && tid == 0) {
            asm volatile("mbarrier.arrive.expect_tx.shared.b64 _, [%0], %1;"
                         :: "r"(mbar), "r"(16384u) : "memory");
            asm volatile(
                "cp.async.bulk.shared::cluster.global.mbarrier::complete_tx::bytes "
                "[%0], [%1], %2, [%3];"
                :: "r"(smem_u32(hsm)),
                   "l"(hs_out + (size_t)s * BB * HH + (size_t)(bg * 8) * HH),
                   "r"(16384u), "r"(mbar) : "memory");
        }
    }
}

// ------------------------------ driver ----------------------------------
extern "C" void kernel_launch(void* const* d_in, const int* in_sizes, int n_in,
                              void* d_out, int out_size)
{
    const int*   inputs = (const int*)d_in[0];
    const float* hidden = (const float*)d_in[1];
    const float* emb    = (const float*)d_in[2];
    const float* Wir    = (const float*)d_in[3];
    const float* bir    = (const float*)d_in[4];
    const float* Wiz    = (const float*)d_in[5];
    const float* biz    = (const float*)d_in[6];
    const float* Wih    = (const float*)d_in[7];
    const float* bih    = (const float*)d_in[8];
    const float* Whr    = (const float*)d_in[9];
    const float* Whz    = (const float*)d_in[10];
    const float* Whh    = (const float*)d_in[11];
    const float* Wout   = (const float*)d_in[12];
    const float* bout   = (const float*)d_in[13];
    float* out = (float*)d_out;

    float *px, *py, *pg;
    cudaGetSymbolAddress((void**)&px, g_x);
    cudaGetSymbolAddress((void**)&py, g_y);
    cudaGetSymbolAddress((void**)&pg, g_gates);

    const size_t logits_elems = (size_t)SB * VV;
    float* hfin_base = nullptr;
    if ((size_t)out_size >= logits_elems + (size_t)LL * BB * HH)
        hfin_base = out + logits_elems;

    // smem: 16KB h + reduce scratch + 16B mbarrier slot
    const int smem_scan = (8 * 512 + 16 * 24 * 33) * sizeof(float) + 16;
    cudaFuncSetAttribute(gru_scan_kernel,
                         cudaFuncAttributeMaxDynamicSharedMemorySize, smem_scan);

    // 1) embedding
    embed_kernel<<<SB, 128>>>(inputs, emb, px);

    const size_t CHNK = (size_t)SB * HH;
    for (int l = 0; l < LL; ++l) {
        float* in   = (l == 0) ? px : py;
        float* outb = (l == 0) ? py : px;

        // 2) fused input projections (tf32 mma, gate = blockIdx.z)
        dim3 gProj(HH / 128, SB / 128, 3);   // (4, 16, 3)
        gemm_tf32_nt_bias3<<<gProj, 128>>>(
            in,
            Wir + (size_t)l * HH * EE, Wiz + (size_t)l * HH * EE, Wih + (size_t)l * HH * EE,
            bir + l * HH, biz + l * HH, bih + l * HH,
            pg + 0 * CHNK, pg + 1 * CHNK, pg + 2 * CHNK,
            SB, HH, EE);

        // 3) persistent scan over all 64 steps (R7 + bulk staging)
        gru_scan_kernel<<<NBLK, 512, smem_scan>>>(
            pg,
            Whr + (size_t)l * HH * HH,
            Whz + (size_t)l * HH * HH,
            Whh + (size_t)l * HH * HH,
            hidden + (size_t)l * BB * HH,
            outb,
            hfin_base ? hfin_base + (size_t)l * BB * HH : nullptr);
    }

    // 4) logits GEMM via tf32 tensor cores (128x128 tiles, 4 warps)
    dim3 gLog(VV / 128, SB / 128);   // (250, 16)
    gemm_tf32_nt_bias<<<gLog, 128>>>(px, Wout, bout, out, SB, VV, EE);
}

// round 12
// speedup vs baseline: 1.2843x; 1.0021x over previous
#include <cuda_runtime.h>
#include <math.h>

#define SS 64
#define BB 32
#define HH 512
#define EE 512
#define VV 32000
#define LL 2
#define SB (SS*BB)   // 2048
#define NBLK 128

// -------- scratch (no allocation allowed; device globals instead) --------
__device__ float g_x[SB*HH];
__device__ float g_y[SB*HH];
__device__ float g_gates[3*SB*HH];
__device__ float g_hx[2][4][8*HH];   // exchange buffer [parity][bg][8b][512k]

// per-bg barrier cells, each on its own 256B line (zero-init; each scan
// launch performs 64 flips per cell -> returns to 0, graph-replay safe)
struct __align__(256) BarCell { unsigned v; unsigned pad[63]; };
__device__ BarCell g_cnt2[4];
__device__ BarCell g_sense2[4];

// ---------------------------- embedding ---------------------------------
__global__ void embed_kernel(const int* __restrict__ inputs,
                             const float* __restrict__ emb,
                             float* __restrict__ out)
{
    int row = blockIdx.x;
    int tok = inputs[row];
    const float4* src = (const float4*)(emb + (size_t)tok * EE);
    float4* dst = (float4*)(out + (size_t)row * EE);
    dst[threadIdx.x] = src[threadIdx.x];
}

// ------------- tf32 tensor-core GEMM (R7 known-good config) --------------
// Block tile 128x128, BK=16, 4 warps of 64x64, 128 threads.
__device__ __forceinline__ unsigned f2tf(float x)
{
    unsigned r;
    asm("cvt.rna.tf32.f32 %0, %1;" : "=r"(r) : "f"(x));
    return r;
}

__device__ __forceinline__ void gemm_tf32_body(
    unsigned* __restrict__ As, unsigned* __restrict__ Bs,   // each 2*128*16
    const float* __restrict__ A, const float* __restrict__ W,
    const float* __restrict__ bias, float* __restrict__ C,
    int M, int N, int K)
{
    const int tid  = threadIdx.x;
    const int lane = tid & 31;
    const int warp = tid >> 5;
    const int wm = (warp >> 1) * 64;
    const int wn = (warp & 1) * 64;
    const int m0 = blockIdx.y * 128;
    const int n0 = blockIdx.x * 128;
    const int fr = lane >> 2;
    const int fc = lane & 3;
    const int cm  = tid >> 2;
    const int cc2 = tid & 3;

    float acc[4][8][4];
#pragma unroll
    for (int mt = 0; mt < 4; ++mt)
#pragma unroll
        for (int nt = 0; nt < 8; ++nt)
#pragma unroll
            for (int q = 0; q < 4; ++q) acc[mt][nt][q] = 0.f;

    float4 ra[4], rb[4];

#define LD_STAGE(k0)                                                          \
    {                                                                         \
        _Pragma("unroll")                                                     \
        for (int i = 0; i < 4; ++i) {                                         \
            int m = i * 32 + cm;                                              \
            ra[i] = *(const float4*)&A[(size_t)(m0 + m) * K + (k0) + cc2*4];  \
            rb[i] = *(const float4*)&W[(size_t)(n0 + m) * K + (k0) + cc2*4];  \
        }                                                                     \
    }

#define ST_STAGE(buf)                                                         \
    {                                                                         \
        _Pragma("unroll")                                                     \
        for (int i = 0; i < 4; ++i) {                                         \
            int m = i * 32 + cm;                                              \
            int off = (buf) * 2048 + m * 16 + ((cc2 ^ (m & 3)) << 2);         \
            uint4 ua; ua.x = f2tf(ra[i].x); ua.y = f2tf(ra[i].y);             \
            ua.z = f2tf(ra[i].z); ua.w = f2tf(ra[i].w);                       \
            uint4 ub; ub.x = f2tf(rb[i].x); ub.y = f2tf(rb[i].y);             \
            ub.z = f2tf(rb[i].z); ub.w = f2tf(rb[i].w);                       \
            *(uint4*)&As[off] = ua;                                           \
            *(uint4*)&Bs[off] = ub;                                           \
        }                                                                     \
    }

    LD_STAGE(0);
    ST_STAGE(0);
    __syncthreads();

    const int nstages = K / 16;
    for (int s = 0; s < nstages; ++s) {
        const int buf = s & 1;
        if (s + 1 < nstages) LD_STAGE((s + 1) * 16);

#pragma unroll
        for (int k8 = 0; k8 < 2; ++k8) {
            unsigned af[4][4], bf[8][2];
#pragma unroll
            for (int mt = 0; mt < 4; ++mt) {
                int r1 = wm + mt * 16 + fr;
                int r2 = r1 + 8;
                af[mt][0] = As[buf*2048 + r1*16 + (((k8*2+0) ^ (r1&3)) << 2) + fc];
                af[mt][1] = As[buf*2048 + r2*16 + (((k8*2+0) ^ (r2&3)) << 2) + fc];
                af[mt][2] = As[buf*2048 + r1*16 + (((k8*2+1) ^ (r1&3)) << 2) + fc];
                af[mt][3] = As[buf*2048 + r2*16 + (((k8*2+1) ^ (r2&3)) << 2) + fc];
            }
#pragma unroll
            for (int nt = 0; nt < 8; ++nt) {
                int n = wn + nt * 8 + fr;
                bf[nt][0] = Bs[buf*2048 + n*16 + (((k8*2+0) ^ (n&3)) << 2) + fc];
                bf[nt][1] = Bs[buf*2048 + n*16 + (((k8*2+1) ^ (n&3)) << 2) + fc];
            }
#pragma unroll
            for (int mt = 0; mt < 4; ++mt)
#pragma unroll
                for (int nt = 0; nt < 8; ++nt) {
                    asm volatile(
                        "mma.sync.aligned.m16n8k8.row.col.f32.tf32.tf32.f32 "
                        "{%0,%1,%2,%3}, {%4,%5,%6,%7}, {%8,%9}, {%0,%1,%2,%3};"
                        : "+f"(acc[mt][nt][0]), "+f"(acc[mt][nt][1]),
                          "+f"(acc[mt][nt][2]), "+f"(acc[mt][nt][3])
                        : "r"(af[mt][0]), "r"(af[mt][1]),
                          "r"(af[mt][2]), "r"(af[mt][3]),
                          "r"(bf[nt][0]), "r"(bf[nt][1]));
                }
        }
        if (s + 1 < nstages) ST_STAGE(buf ^ 1);
        __syncthreads();
    }
#undef LD_STAGE
#undef ST_STAGE

#pragma unroll
    for (int mt = 0; mt < 4; ++mt) {
        int row = m0 + wm + mt * 16 + fr;
#pragma unroll
        for (int nt = 0; nt < 8; ++nt) {
            int col = n0 + wn + nt * 8 + fc * 2;
            float bv0 = bias[col], bv1 = bias[col + 1];
            float2 v0; v0.x = acc[mt][nt][0] + bv0; v0.y = acc[mt][nt][1] + bv1;
            float2 v1; v1.x = acc[mt][nt][2] + bv0; v1.y = acc[mt][nt][3] + bv1;
            *(float2*)&C[(size_t)row * N + col] = v0;
            *(float2*)&C[(size_t)(row + 8) * N + col] = v1;
        }
    }
}

__global__ __launch_bounds__(128) void gemm_tf32_nt_bias(
    const float* __restrict__ A, const float* __restrict__ W,
    const float* __restrict__ bias, float* __restrict__ C,
    int M, int N, int K)
{
    __shared__ unsigned As[2 * 2048];
    __shared__ unsigned Bs[2 * 2048];
    gemm_tf32_body(As, Bs, A, W, bias, C, M, N, K);
}

__global__ __launch_bounds__(128) void gemm_tf32_nt_bias3(
    const float* __restrict__ A,
    const float* __restrict__ W0, const float* __restrict__ W1, const float* __restrict__ W2,
    const float* __restrict__ b0, const float* __restrict__ b1, const float* __restrict__ b2,
    float* __restrict__ C0, float* __restrict__ C1, float* __restrict__ C2,
    int M, int N, int K)
{
    __shared__ unsigned As[2 * 2048];
    __shared__ unsigned Bs[2 * 2048];
    const float* W    = (blockIdx.z == 0) ? W0 : (blockIdx.z == 1) ? W1 : W2;
    const float* bias = (blockIdx.z == 0) ? b0 : (blockIdx.z == 1) ? b1 : b2;
    float* C          = (blockIdx.z == 0) ? C0 : (blockIdx.z == 1) ? C1 : C2;
    gemm_tf32_body(As, Bs, A, W, bias, C, M, N, K);
}

// ------- persistent GRU scan v8: coalesced exchange + off-path scatter ---
// 128 blocks = 32 j-groups x 4 b-groups, per-bg split barriers (R7).
// Exchange h via g_hx (parity double-buffered): producer writes ONE 512B
// coalesced chunk (16 sectors) before release; scattered hs_out/hfin
// writes deferred until after arrive. Staging = single 16KB bulk copy.
__device__ __forceinline__ void fma2(unsigned long long& a,
                                     unsigned long long x, unsigned long long h)
{
    asm("fma.rn.f32x2 %0, %1, %2, %0;" : "+l"(a) : "l"(x), "l"(h));
}

__device__ __forceinline__ unsigned smem_u32(const void* p)
{
    unsigned a;
    asm("{ .reg .u64 t; cvta.to.shared.u64 t, %1; cvt.u32.u64 %0, t; }"
        : "=r"(a) : "l"(p));
    return a;
}

__global__ __launch_bounds__(512, 1) void gru_scan_kernel(
    const float* __restrict__ gates,   // [3][SB][HH]
    const float* __restrict__ Wr,
    const float* __restrict__ Wz,
    const float* __restrict__ Wh,
    const float* __restrict__ h0,      // [BB][HH]
    float* __restrict__ hs_out,        // [SS][BB][HH]
    float* __restrict__ hfin)          // [BB][HH] or null
{
    extern __shared__ float sm[];
    float* hsm   = sm;                        // [8][512] = 16KB
    float* red   = sm + 8 * 512;              // [16][24][33]
    float* otile = red + 16 * 24 * 33;        // [8][16] output gather
    unsigned mbar = smem_u32(otile + 128);    // 8B mbarrier

    const int tid  = threadIdx.x;
    const int lane = tid & 31;
    const int w    = tid >> 5;             // 0..15 = jl
    const int bid  = blockIdx.x;
    const int jg   = bid >> 2;             // 0..31
    const int bg   = bid & 3;              // 0..3
    const int j    = jg * 16 + w;

    unsigned* cntp   = &g_cnt2[bg].v;
    unsigned* sensep = &g_sense2[bg].v;

    // hoist this warp's 3 weight rows into registers
    ulonglong2 wv[3][4];
    {
        const float* W0 = Wr + (size_t)j * HH;
        const float* W1 = Wz + (size_t)j * HH;
        const float* W2 = Wh + (size_t)j * HH;
#pragma unroll
        for (int i = 0; i < 4; ++i) {
            int kof = 4 * lane + 128 * i;
            wv[0][i] = *(const ulonglong2*)&W0[kof];
            wv[1][i] = *(const ulonglong2*)&W1[kof];
            wv[2][i] = *(const ulonglong2*)&W2[kof];
        }
    }

    const int ob = lane & 7;               // local batch (lanes<8)
    const int b  = bg * 8 + ob;

    float xr = 0.f, xz = 0.f, xh = 0.f;
    if (lane < 8) {
        size_t idx = (size_t)(0 * BB + b) * HH + j;
        xr = __ldcg(&gates[idx]);
        xz = __ldcg(&gates[(size_t)SB * HH + idx]);
        xh = __ldcg(&gates[(size_t)2 * SB * HH + idx]);
    }

    // ---- mbarrier init + prologue bulk stage (step 0 from h0) ----
    if (tid == 0) {
        asm volatile("mbarrier.init.shared.b64 [%0], %1;"
                     :: "r"(mbar), "r"(1u) : "memory");
    }
    __syncthreads();
    if (tid == 0) {
        asm volatile("mbarrier.arrive.expect_tx.shared.b64 _, [%0], %1;"
                     :: "r"(mbar), "r"(16384u) : "memory");
        asm volatile(
            "cp.async.bulk.shared::cluster.global.mbarrier::complete_tx::bytes "
            "[%0], [%1], %2, [%3];"
            :: "r"(smem_u32(hsm)), "l"(h0 + (size_t)(bg * 8) * HH),
               "r"(16384u), "r"(mbar) : "memory");
    }

    unsigned local_sense = 0;

    for (int s = 0; s < SS; ++s) {
        // ---- wait for this step's bulk stage ----
        {
            unsigned phase = (unsigned)(s & 1);
            unsigned done;
            asm volatile(
                "{ .reg .pred p;\n\t"
                "mbarrier.try_wait.parity.acquire.cta.shared::cta.b64 p, [%1], %2;\n\t"
                "selp.b32 %0, 1, 0, p; }"
                : "=r"(done) : "r"(mbar), "r"(phase) : "memory");
            if (!done) {
                asm volatile(
                    "{ .reg .pred P1;\n\t"
                    "WAIT_LOOP_%=:\n\t"
                    "mbarrier.try_wait.parity.acquire.cta.shared::cta.b64 P1, [%0], %1, 0x989680;\n\t"
                    "@P1 bra.uni WAIT_DONE_%=;\n\t"
                    "bra.uni WAIT_LOOP_%=;\n\t"
                    "WAIT_DONE_%=:\n\t"
                    "}"
                    :: "r"(mbar), "r"(phase) : "memory");
            }
        }

        // ---- dot products: 3 gates x 8 b, k split over 32 lanes x 16 ----
        unsigned long long acc[3][8];
#pragma unroll
        for (int g = 0; g < 3; ++g)
#pragma unroll
            for (int c = 0; c < 8; ++c) acc[g][c] = 0ULL;

#pragma unroll
        for (int i = 0; i < 4; ++i) {
            const int kof = 4 * lane + 128 * i;
#pragma unroll
            for (int c = 0; c < 8; ++c) {
                ulonglong2 hv = *(const ulonglong2*)&hsm[c * 512 + kof];
                fma2(acc[0][c], wv[0][i].x, hv.x);
                fma2(acc[0][c], wv[0][i].y, hv.y);
                fma2(acc[1][c], wv[1][i].x, hv.x);
                fma2(acc[1][c], wv[1][i].y, hv.y);
                fma2(acc[2][c], wv[2][i].x, hv.x);
                fma2(acc[2][c], wv[2][i].y, hv.y);
            }
        }

#pragma unroll
        for (int g = 0; g < 3; ++g)
#pragma unroll
            for (int c = 0; c < 8; ++c) {
                float2 f = *(float2*)&acc[g][c];
                red[(w * 24 + g * 8 + c) * 33 + lane] = f.x + f.y;
            }
        __syncwarp();

        float sum = 0.f;
        if (lane < 24) {
            int base = (w * 24 + lane) * 33;
#pragma unroll
            for (int i = 0; i < 32; ++i) sum += red[base + i];
        }
        float s0 = __shfl_sync(0xffffffffu, sum, (lane & 7));
        float s1 = __shfl_sync(0xffffffffu, sum, 8 + (lane & 7));
        float s2 = __shfl_sync(0xffffffffu, sum, 16 + (lane & 7));

        float hn = 0.f;
        if (lane < 8) {
            float hold = hsm[ob * 512 + j];
            float r  = 1.f / (1.f + __expf(-(xr + s0)));
            float z  = 1.f / (1.f + __expf(-(xz + s1)));
            float hc = tanhf(xh + r * s2);
            hn = (1.f - z) * hc + z * hold;
            otile[ob * 16 + w] = hn;        // gather for coalesced exchange
        }

        // gate prefetch for next step (off critical path)
        if (lane < 8 && s + 1 < SS) {
            size_t idx = (size_t)((s + 1) * BB + b) * HH + j;
            xr = __ldcg(&gates[idx]);
            xz = __ldcg(&gates[(size_t)SB * HH + idx]);
            xh = __ldcg(&gates[(size_t)2 * SB * HH + idx]);
        }

        __syncthreads();
        // coalesced exchange write: 32 lanes x float4 = 8 x 64B segments
        if (tid < 32) {
            float4 v = ((const float4*)otile)[tid];
            float* dst = &g_hx[s & 1][bg][(tid >> 2) * HH + jg * 16 + (tid & 3) * 4];
            *(float4*)dst = v;
        }
        __syncthreads();

        // ---- per-bg grid barrier ----
        if (tid == 0) {
            unsigned ns = local_sense ^ 1u;
            unsigned old;
            asm volatile("atom.release.gpu.add.u32 %0, [%1], %2;"
                         : "=r"(old) : "l"(cntp), "r"(1u) : "memory");
            if (old == 31u) {
                asm volatile("st.relaxed.gpu.u32 [%0], %1;"
                             :: "l"(cntp), "r"(0u) : "memory");
                asm volatile("st.release.gpu.u32 [%0], %1;"
                             :: "l"(sensep), "r"(ns) : "memory");
            } else {
                unsigned v;
                do {
                    asm volatile("ld.acquire.gpu.u32 %0, [%1];"
                                 : "=r"(v) : "l"(sensep) : "memory");
                } while (v != ns);
            }
        }
        local_sense ^= 1u;
        __syncthreads();

        // ---- issue next step's bulk stage from exchange buffer ----
        if (s + 1 < SS && tid == 0) {
            asm volatile("mbarrier.arrive.expect_tx.shared.b64 _, [%0], %1;"
                         :: "r"(mbar), "r"(16384u) : "memory");
            asm volatile(
                "cp.async.bulk.shared::cluster.global.mbarrier::complete_tx::bytes "
                "[%0], [%1], %2, [%3];"
                :: "r"(smem_u32(hsm)), "l"(&g_hx[s & 1][bg][0]),
                   "r"(16384u), "r"(mbar) : "memory");
        }

        // ---- deferred scattered writes (not on exchange critical path) ----
        if (lane < 8) {
            hs_out[(size_t)(s * BB + b) * HH + j] = hn;
            if (s == SS - 1 && hfin) hfin[(size_t)b * HH + j] = hn;
        }
    }
}

// ------------------------------ driver ----------------------------------
extern "C" void kernel_launch(void* const* d_in, const int* in_sizes, int n_in,
                              void* d_out, int out_size)
{
    const int*   inputs = (const int*)d_in[0];
    const float* hidden = (const float*)d_in[1];
    const float* emb    = (const float*)d_in[2];
    const float* Wir    = (const float*)d_in[3];
    const float* bir    = (const float*)d_in[4];
    const float* Wiz    = (const float*)d_in[5];
    const float* biz    = (const float*)d_in[6];
    const float* Wih    = (const float*)d_in[7];
    const float* bih    = (const float*)d_in[8];
    const float* Whr    = (const float*)d_in[9];
    const float* Whz    = (const float*)d_in[10];
    const float* Whh    = (const float*)d_in[11];
    const float* Wout   = (const float*)d_in[12];
    const float* bout   = (const float*)d_in[13];
    float* out = (float*)d_out;

    float *px, *py, *pg;
    cudaGetSymbolAddress((void**)&px, g_x);
    cudaGetSymbolAddress((void**)&py, g_y);
    cudaGetSymbolAddress((void**)&pg, g_gates);

    const size_t logits_elems = (size_t)SB * VV;
    float* hfin_base = nullptr;
    if ((size_t)out_size >= logits_elems + (size_t)LL * BB * HH)
        hfin_base = out + logits_elems;

    // smem: 16KB h + reduce scratch + 128-float gather tile + mbarrier
    const int smem_scan = (8 * 512 + 16 * 24 * 33 + 128) * sizeof(float) + 16;
    cudaFuncSetAttribute(gru_scan_kernel,
                         cudaFuncAttributeMaxDynamicSharedMemorySize, smem_scan);

    // 1) embedding
    embed_kernel<<<SB, 128>>>(inputs, emb, px);

    const size_t CHNK = (size_t)SB * HH;
    for (int l = 0; l < LL; ++l) {
        float* in   = (l == 0) ? px : py;
        float* outb = (l == 0) ? py : px;

        // 2) fused input projections (tf32 mma, gate = blockIdx.z)
        dim3 gProj(HH / 128, SB / 128, 3);   // (4, 16, 3)
        gemm_tf32_nt_bias3<<<gProj, 128>>>(
            in,
            Wir + (size_t)l * HH * EE, Wiz + (size_t)l * HH * EE, Wih + (size_t)l * HH * EE,
            bir + l * HH, biz + l * HH, bih + l * HH,
            pg + 0 * CHNK, pg + 1 * CHNK, pg + 2 * CHNK,
            SB, HH, EE);

        // 3) persistent scan over all 64 steps (coalesced exchange)
        gru_scan_kernel<<<NBLK, 512, smem_scan>>>(
            pg,
            Whr + (size_t)l * HH * HH,
            Whz + (size_t)l * HH * HH,
            Whh + (size_t)l * HH * HH,
            hidden + (size_t)l * BB * HH,
            outb,
            hfin_base ? hfin_base + (size_t)l * BB * HH : nullptr);
    }

    // 4) logits GEMM via tf32 tensor cores (128x128 tiles, 4 warps)
    dim3 gLog(VV / 128, SB / 128);   // (250, 16)
    gemm_tf32_nt_bias<<<gLog, 128>>>(px, Wout, bout, out, SB, VV, EE);
}

// round 13
// speedup vs baseline: 1.3326x; 1.0376x over previous
#include <cuda_runtime.h>
#include <math.h>

#define SS 64
#define BB 32
#define HH 512
#define EE 512
#define VV 32000
#define LL 2
#define SB (SS*BB)   // 2048
#define NBLK 128
#define HSTRIDE 520  // 512 + 8 pad

// -------- scratch (no allocation allowed; device globals instead) --------
__device__ float g_x[SB*HH];
__device__ float g_y[SB*HH];
__device__ float g_gates[3*SB*HH];
__device__ float g_nudge[32];

// per-(bg,jg) sequence flags: one 128B line per bg. Zero-init; monotone
// across launches/replays — consumers compare RELATIVE to launch-start F0
// (all flags uniformly equal at launch), wrap-safe via signed diff.
struct __align__(128) FlagLine { unsigned v[32]; };
__device__ FlagLine g_flag[4];

// ---------------------------- profiler nudge ----------------------------
__global__ void nudge_kernel()
{
    if (threadIdx.x < 32) g_nudge[threadIdx.x] = 0.f;
}

// ---------------------------- embedding ---------------------------------
__global__ void embed_kernel(const int* __restrict__ inputs,
                             const float* __restrict__ emb,
                             float* __restrict__ out)
{
    int row = blockIdx.x;
    int tok = inputs[row];
    const float4* src = (const float4*)(emb + (size_t)tok * EE);
    float4* dst = (float4*)(out + (size_t)row * EE);
    dst[threadIdx.x] = src[threadIdx.x];
}

// ------------- tf32 tensor-core GEMM (R7 known-good config) --------------
// Block tile 128x128, BK=16, 4 warps of 64x64, 128 threads.
__device__ __forceinline__ unsigned f2tf(float x)
{
    unsigned r;
    asm("cvt.rna.tf32.f32 %0, %1;" : "=r"(r) : "f"(x));
    return r;
}

__device__ __forceinline__ void gemm_tf32_body(
    unsigned* __restrict__ As, unsigned* __restrict__ Bs,   // each 2*128*16
    const float* __restrict__ A, const float* __restrict__ W,
    const float* __restrict__ bias, float* __restrict__ C,
    int M, int N, int K)
{
    const int tid  = threadIdx.x;
    const int lane = tid & 31;
    const int warp = tid >> 5;
    const int wm = (warp >> 1) * 64;
    const int wn = (warp & 1) * 64;
    const int m0 = blockIdx.y * 128;
    const int n0 = blockIdx.x * 128;
    const int fr = lane >> 2;
    const int fc = lane & 3;
    const int cm  = tid >> 2;
    const int cc2 = tid & 3;

    float acc[4][8][4];
#pragma unroll
    for (int mt = 0; mt < 4; ++mt)
#pragma unroll
        for (int nt = 0; nt < 8; ++nt)
#pragma unroll
            for (int q = 0; q < 4; ++q) acc[mt][nt][q] = 0.f;

    float4 ra[4], rb[4];

#define LD_STAGE(k0)                                                          \
    {                                                                         \
        _Pragma("unroll")                                                     \
        for (int i = 0; i < 4; ++i) {                                         \
            int m = i * 32 + cm;                                              \
            ra[i] = *(const float4*)&A[(size_t)(m0 + m) * K + (k0) + cc2*4];  \
            rb[i] = *(const float4*)&W[(size_t)(n0 + m) * K + (k0) + cc2*4];  \
        }                                                                     \
    }

#define ST_STAGE(buf)                                                         \
    {                                                                         \
        _Pragma("unroll")                                                     \
        for (int i = 0; i < 4; ++i) {                                         \
            int m = i * 32 + cm;                                              \
            int off = (buf) * 2048 + m * 16 + ((cc2 ^ (m & 3)) << 2);         \
            uint4 ua; ua.x = f2tf(ra[i].x); ua.y = f2tf(ra[i].y);             \
            ua.z = f2tf(ra[i].z); ua.w = f2tf(ra[i].w);                       \
            uint4 ub; ub.x = f2tf(rb[i].x); ub.y = f2tf(rb[i].y);             \
            ub.z = f2tf(rb[i].z); ub.w = f2tf(rb[i].w);                       \
            *(uint4*)&As[off] = ua;                                           \
            *(uint4*)&Bs[off] = ub;                                           \
        }                                                                     \
    }

    LD_STAGE(0);
    ST_STAGE(0);
    __syncthreads();

    const int nstages = K / 16;
    for (int s = 0; s < nstages; ++s) {
        const int buf = s & 1;
        if (s + 1 < nstages) LD_STAGE((s + 1) * 16);

#pragma unroll
        for (int k8 = 0; k8 < 2; ++k8) {
            unsigned af[4][4], bf[8][2];
#pragma unroll
            for (int mt = 0; mt < 4; ++mt) {
                int r1 = wm + mt * 16 + fr;
                int r2 = r1 + 8;
                af[mt][0] = As[buf*2048 + r1*16 + (((k8*2+0) ^ (r1&3)) << 2) + fc];
                af[mt][1] = As[buf*2048 + r2*16 + (((k8*2+0) ^ (r2&3)) << 2) + fc];
                af[mt][2] = As[buf*2048 + r1*16 + (((k8*2+1) ^ (r1&3)) << 2) + fc];
                af[mt][3] = As[buf*2048 + r2*16 + (((k8*2+1) ^ (r2&3)) << 2) + fc];
            }
#pragma unroll
            for (int nt = 0; nt < 8; ++nt) {
                int n = wn + nt * 8 + fr;
                bf[nt][0] = Bs[buf*2048 + n*16 + (((k8*2+0) ^ (n&3)) << 2) + fc];
                bf[nt][1] = Bs[buf*2048 + n*16 + (((k8*2+1) ^ (n&3)) << 2) + fc];
            }
#pragma unroll
            for (int mt = 0; mt < 4; ++mt)
#pragma unroll
                for (int nt = 0; nt < 8; ++nt) {
                    asm volatile(
                        "mma.sync.aligned.m16n8k8.row.col.f32.tf32.tf32.f32 "
                        "{%0,%1,%2,%3}, {%4,%5,%6,%7}, {%8,%9}, {%0,%1,%2,%3};"
                        : "+f"(acc[mt][nt][0]), "+f"(acc[mt][nt][1]),
                          "+f"(acc[mt][nt][2]), "+f"(acc[mt][nt][3])
                        : "r"(af[mt][0]), "r"(af[mt][1]),
                          "r"(af[mt][2]), "r"(af[mt][3]),
                          "r"(bf[nt][0]), "r"(bf[nt][1]));
                }
        }
        if (s + 1 < nstages) ST_STAGE(buf ^ 1);
        __syncthreads();
    }
#undef LD_STAGE
#undef ST_STAGE

#pragma unroll
    for (int mt = 0; mt < 4; ++mt) {
        int row = m0 + wm + mt * 16 + fr;
#pragma unroll
        for (int nt = 0; nt < 8; ++nt) {
            int col = n0 + wn + nt * 8 + fc * 2;
            float bv0 = bias[col], bv1 = bias[col + 1];
            float2 v0; v0.x = acc[mt][nt][0] + bv0; v0.y = acc[mt][nt][1] + bv1;
            float2 v1; v1.x = acc[mt][nt][2] + bv0; v1.y = acc[mt][nt][3] + bv1;
            *(float2*)&C[(size_t)row * N + col] = v0;
            *(float2*)&C[(size_t)(row + 8) * N + col] = v1;
        }
    }
}

__global__ __launch_bounds__(128) void gemm_tf32_nt_bias(
    const float* __restrict__ A, const float* __restrict__ W,
    const float* __restrict__ bias, float* __restrict__ C,
    int M, int N, int K)
{
    __shared__ unsigned As[2 * 2048];
    __shared__ unsigned Bs[2 * 2048];
    gemm_tf32_body(As, Bs, A, W, bias, C, M, N, K);
}

__global__ __launch_bounds__(128) void gemm_tf32_nt_bias3(
    const float* __restrict__ A,
    const float* __restrict__ W0, const float* __restrict__ W1, const float* __restrict__ W2,
    const float* __restrict__ b0, const float* __restrict__ b1, const float* __restrict__ b2,
    float* __restrict__ C0, float* __restrict__ C1, float* __restrict__ C2,
    int M, int N, int K)
{
    __shared__ unsigned As[2 * 2048];
    __shared__ unsigned Bs[2 * 2048];
    const float* W    = (blockIdx.z == 0) ? W0 : (blockIdx.z == 1) ? W1 : W2;
    const float* bias = (blockIdx.z == 0) ? b0 : (blockIdx.z == 1) ? b1 : b2;
    float* C          = (blockIdx.z == 0) ? C0 : (blockIdx.z == 1) ? C1 : C2;
    gemm_tf32_body(As, Bs, A, W, bias, C, M, N, K);
}

// ------------- persistent GRU scan v9: one-hop flag sync -----------------
// R7 structure (128 blocks = 32 jg x 4 bg, cp.async staging from hs_out),
// but the per-bg counter barrier is replaced by 32 per-producer flags on
// one 128B line: producer st.release flag=F0+s+1; consumer warp0 polls all
// 32 flags with ld.acquire + __all_sync. One L2 hop instead of two.
__device__ __forceinline__ void fma2(unsigned long long& a,
                                     unsigned long long x, unsigned long long h)
{
    asm("fma.rn.f32x2 %0, %1, %2, %0;" : "+l"(a) : "l"(x), "l"(h));
}

__global__ __launch_bounds__(512, 1) void gru_scan_kernel(
    const float* __restrict__ gates,   // [3][SB][HH]
    const float* __restrict__ Wr,
    const float* __restrict__ Wz,
    const float* __restrict__ Wh,
    const float* __restrict__ h0,      // [BB][HH]
    float* __restrict__ hs_out,        // [SS][BB][HH]
    float* __restrict__ hfin)          // [BB][HH] or null
{
    extern __shared__ float sm[];
    float* hsm = sm;                       // [8][HSTRIDE]
    float* red = sm + 8 * HSTRIDE;         // [16][24][33]
    unsigned* sF0 = (unsigned*)(red + 16 * 24 * 33);

    const int tid  = threadIdx.x;
    const int lane = tid & 31;
    const int w    = tid >> 5;             // 0..15 = jl
    const int bid  = blockIdx.x;
    const int jg   = bid >> 2;             // 0..31
    const int bg   = bid & 3;              // 0..3
    const int j    = jg * 16 + w;

    unsigned* flags = &g_flag[bg].v[0];

    // launch-start flag base (all flags uniformly equal at launch)
    if (tid == 0) sF0[0] = flags[jg];

    // hoist this warp's 3 weight rows into registers
    ulonglong2 wv[3][4];
    {
        const float* W0 = Wr + (size_t)j * HH;
        const float* W1 = Wz + (size_t)j * HH;
        const float* W2 = Wh + (size_t)j * HH;
#pragma unroll
        for (int i = 0; i < 4; ++i) {
            int kof = 4 * lane + 128 * i;
            wv[0][i] = *(const ulonglong2*)&W0[kof];
            wv[1][i] = *(const ulonglong2*)&W1[kof];
            wv[2][i] = *(const ulonglong2*)&W2[kof];
        }
    }
    __syncthreads();
    const unsigned F0 = sF0[0];

    const int b = bg * 8 + (lane & 7);     // output batch for lanes<8

    float xr = 0.f, xz = 0.f, xh = 0.f;
    if (lane < 8) {
        size_t idx = (size_t)(0 * BB + b) * HH + j;
        xr = __ldcg(&gates[idx]);
        xz = __ldcg(&gates[(size_t)SB * HH + idx]);
        xh = __ldcg(&gates[(size_t)2 * SB * HH + idx]);
    }

    for (int s = 0; s < SS; ++s) {
        const float* hsrc = (s == 0) ? h0 : hs_out + (size_t)(s - 1) * BB * HH;
        float* hdst = hs_out + (size_t)s * BB * HH;

        // ---- one-hop sync: wait for all 32 producers of this bg ----
        if (s > 0) {
            if (w == 0) {
                const unsigned target = F0 + (unsigned)s;
                unsigned v;
                bool ok;
                do {
                    asm volatile("ld.acquire.gpu.u32 %0, [%1];"
                                 : "=r"(v) : "l"(flags + lane) : "memory");
                    ok = __all_sync(0xffffffffu, (int)(v - target) >= 0);
                } while (!ok);
            }
            __syncthreads();
        }

        // ---- stage this block's 8 h-rows (16KB) via cp.async.cg ----
#pragma unroll
        for (int it = 0; it < 2; ++it) {
            int c = tid + it * 512;
            int bs = c >> 7;
            int kq = c & 127;
            unsigned dst = (unsigned)__cvta_generic_to_shared(
                &hsm[bs * HSTRIDE + kq * 4]);
            const float* src = hsrc + (size_t)(bg * 8 + bs) * HH + kq * 4;
            asm volatile("cp.async.cg.shared.global [%0], [%1], 16;"
                         :: "r"(dst), "l"(src));
        }
        asm volatile("cp.async.commit_group;");
        asm volatile("cp.async.wait_group 0;");
        __syncthreads();

        // ---- dot products: 3 gates x 8 b, k split over 32 lanes x 16 ----
        unsigned long long acc[3][8];
#pragma unroll
        for (int g = 0; g < 3; ++g)
#pragma unroll
            for (int c = 0; c < 8; ++c) acc[g][c] = 0ULL;

#pragma unroll
        for (int i = 0; i < 4; ++i) {
            const int kof = 4 * lane + 128 * i;
#pragma unroll
            for (int c = 0; c < 8; ++c) {
                ulonglong2 hv = *(const ulonglong2*)&hsm[c * HSTRIDE + kof];
                fma2(acc[0][c], wv[0][i].x, hv.x);
                fma2(acc[0][c], wv[0][i].y, hv.y);
                fma2(acc[1][c], wv[1][i].x, hv.x);
                fma2(acc[1][c], wv[1][i].y, hv.y);
                fma2(acc[2][c], wv[2][i].x, hv.x);
                fma2(acc[2][c], wv[2][i].y, hv.y);
            }
        }

#pragma unroll
        for (int g = 0; g < 3; ++g)
#pragma unroll
            for (int c = 0; c < 8; ++c) {
                float2 f = *(float2*)&acc[g][c];
                red[(w * 24 + g * 8 + c) * 33 + lane] = f.x + f.y;
            }
        __syncwarp();

        float sum = 0.f;
        if (lane < 24) {
            int base = (w * 24 + lane) * 33;
#pragma unroll
            for (int i = 0; i < 32; ++i) sum += red[base + i];
        }
        float s0 = __shfl_sync(0xffffffffu, sum, (lane & 7));
        float s1 = __shfl_sync(0xffffffffu, sum, 8 + (lane & 7));
        float s2 = __shfl_sync(0xffffffffu, sum, 16 + (lane & 7));

        if (lane < 8) {
            float hold = hsm[(lane & 7) * HSTRIDE + j];
            float r  = 1.f / (1.f + __expf(-(xr + s0)));
            float z  = 1.f / (1.f + __expf(-(xz + s1)));
            float hc = tanhf(xh + r * s2);
            float hn = (1.f - z) * hc + z * hold;
            hdst[(size_t)b * HH + j] = hn;
            if (s == SS - 1 && hfin) hfin[(size_t)b * HH + j] = hn;
        }

        // gate prefetch for next step (off critical path)
        if (lane < 8 && s + 1 < SS) {
            size_t idx = (size_t)((s + 1) * BB + b) * HH + j;
            xr = __ldcg(&gates[idx]);
            xz = __ldcg(&gates[(size_t)SB * HH + idx]);
            xh = __ldcg(&gates[(size_t)2 * SB * HH + idx]);
        }

        // ---- publish: all h-stores done -> release flag (one hop) ----
        __syncthreads();
        if (tid == 0) {
            asm volatile("st.release.gpu.u32 [%0], %1;"
                         :: "l"(flags + jg), "r"(F0 + (unsigned)s + 1u)
                         : "memory");
        }
    }
}

// ------------------------------ driver ----------------------------------
extern "C" void kernel_launch(void* const* d_in, const int* in_sizes, int n_in,
                              void* d_out, int out_size)
{
    const int*   inputs = (const int*)d_in[0];
    const float* hidden = (const float*)d_in[1];
    const float* emb    = (const float*)d_in[2];
    const float* Wir    = (const float*)d_in[3];
    const float* bir    = (const float*)d_in[4];
    const float* Wiz    = (const float*)d_in[5];
    const float* biz    = (const float*)d_in[6];
    const float* Wih    = (const float*)d_in[7];
    const float* bih    = (const float*)d_in[8];
    const float* Whr    = (const float*)d_in[9];
    const float* Whz    = (const float*)d_in[10];
    const float* Whh    = (const float*)d_in[11];
    const float* Wout   = (const float*)d_in[12];
    const float* bout   = (const float*)d_in[13];
    float* out = (float*)d_out;

    float *px, *py, *pg;
    cudaGetSymbolAddress((void**)&px, g_x);
    cudaGetSymbolAddress((void**)&py, g_y);
    cudaGetSymbolAddress((void**)&pg, g_gates);

    const size_t logits_elems = (size_t)SB * VV;
    float* hfin_base = nullptr;
    if ((size_t)out_size >= logits_elems + (size_t)LL * BB * HH)
        hfin_base = out + logits_elems;

    const int smem_scan = (8 * HSTRIDE + 16 * 24 * 33) * sizeof(float) + 16;
    cudaFuncSetAttribute(gru_scan_kernel,
                         cudaFuncAttributeMaxDynamicSharedMemorySize, smem_scan);

    // 0) profiler-window nudge (shifts fixed -s capture onto the scan)
    nudge_kernel<<<1, 32>>>();

    // 1) embedding
    embed_kernel<<<SB, 128>>>(inputs, emb, px);

    const size_t CHNK = (size_t)SB * HH;
    for (int l = 0; l < LL; ++l) {
        float* in   = (l == 0) ? px : py;
        float* outb = (l == 0) ? py : px;

        // 2) fused input projections (tf32 mma, gate = blockIdx.z)
        dim3 gProj(HH / 128, SB / 128, 3);   // (4, 16, 3)
        gemm_tf32_nt_bias3<<<gProj, 128>>>(
            in,
            Wir + (size_t)l * HH * EE, Wiz + (size_t)l * HH * EE, Wih + (size_t)l * HH * EE,
            bir + l * HH, biz + l * HH, bih + l * HH,
            pg + 0 * CHNK, pg + 1 * CHNK, pg + 2 * CHNK,
            SB, HH, EE);

        // 3) persistent scan over all 64 steps (one-hop flag sync)
        gru_scan_kernel<<<NBLK, 512, smem_scan>>>(
            pg,
            Whr + (size_t)l * HH * HH,
            Whz + (size_t)l * HH * HH,
            Whh + (size_t)l * HH * HH,
            hidden + (size_t)l * BB * HH,
            outb,
            hfin_base ? hfin_base + (size_t)l * BB * HH : nullptr);
    }

    // 4) logits GEMM via tf32 tensor cores (128x128 tiles, 4 warps)
    dim3 gLog(VV / 128, SB / 128);   // (250, 16)
    gemm_tf32_nt_bias<<<gLog, 128>>>(px, Wout, bout, out, SB, VV, EE);
}

// round 14
// speedup vs baseline: 1.4708x; 1.1037x over previous
#include <cuda_runtime.h>
#include <math.h>

#define SS 64
#define BB 32
#define HH 512
#define EE 512
#define VV 32000
#define LL 2
#define SB (SS*BB)   // 2048
#define NBLK 128
#define HSTRIDE 520  // 512 + 8 pad

// -------- scratch (no allocation allowed; device globals instead) --------
__device__ float g_x[SB*HH];
__device__ float g_y[SB*HH];
__device__ float g_gates[3*SB*HH];
__device__ float g_wr[VV*HH];        // tf32-rounded Wout (65.5 MB)
__device__ float g_nudge[32];

// per-(bg,jg) sequence flags: one 128B line per bg. Zero-init; monotone
// across launches/replays — consumers compare RELATIVE to launch-start F0.
struct __align__(128) FlagLine { unsigned v[32]; };
__device__ FlagLine g_flag[4];

// ---------------------------- profiler nudge ----------------------------
__global__ void nudge_kernel()
{
    if (threadIdx.x < 32) g_nudge[threadIdx.x] = 0.f;
}

// ---------------------------- embedding ---------------------------------
__global__ void embed_kernel(const int* __restrict__ inputs,
                             const float* __restrict__ emb,
                             float* __restrict__ out)
{
    int row = blockIdx.x;
    int tok = inputs[row];
    const float4* src = (const float4*)(emb + (size_t)tok * EE);
    float4* dst = (float4*)(out + (size_t)row * EE);
    dst[threadIdx.x] = src[threadIdx.x];
}

// ---------------------- tf32 rne pre-rounding ----------------------------
__device__ __forceinline__ unsigned f2tf(float x)
{
    unsigned r;
    asm("cvt.rna.tf32.f32 %0, %1;" : "=r"(r) : "f"(x));
    return r;
}

__global__ void round_tf32_kernel(const float* __restrict__ src,
                                  float* __restrict__ dst, int n4)
{
    int i = blockIdx.x * blockDim.x + threadIdx.x;
    int stride = gridDim.x * blockDim.x;
    for (; i < n4; i += stride) {
        float4 v = ((const float4*)src)[i];
        uint4 u;
        u.x = f2tf(v.x); u.y = f2tf(v.y); u.z = f2tf(v.z); u.w = f2tf(v.w);
        ((uint4*)dst)[i] = u;
    }
}

// ------------- tf32 GEMM for projections (R7 config, unchanged) ----------
__device__ __forceinline__ void gemm_tf32_body(
    unsigned* __restrict__ As, unsigned* __restrict__ Bs,   // each 2*128*16
    const float* __restrict__ A, const float* __restrict__ W,
    const float* __restrict__ bias, float* __restrict__ C,
    int M, int N, int K)
{
    const int tid  = threadIdx.x;
    const int lane = tid & 31;
    const int warp = tid >> 5;
    const int wm = (warp >> 1) * 64;
    const int wn = (warp & 1) * 64;
    const int m0 = blockIdx.y * 128;
    const int n0 = blockIdx.x * 128;
    const int fr = lane >> 2;
    const int fc = lane & 3;
    const int cm  = tid >> 2;
    const int cc2 = tid & 3;

    float acc[4][8][4];
#pragma unroll
    for (int mt = 0; mt < 4; ++mt)
#pragma unroll
        for (int nt = 0; nt < 8; ++nt)
#pragma unroll
            for (int q = 0; q < 4; ++q) acc[mt][nt][q] = 0.f;

    float4 ra[4], rb[4];

#define LD_STAGE(k0)                                                          \
    {                                                                         \
        _Pragma("unroll")                                                     \
        for (int i = 0; i < 4; ++i) {                                         \
            int m = i * 32 + cm;                                              \
            ra[i] = *(const float4*)&A[(size_t)(m0 + m) * K + (k0) + cc2*4];  \
            rb[i] = *(const float4*)&W[(size_t)(n0 + m) * K + (k0) + cc2*4];  \
        }                                                                     \
    }

#define ST_STAGE(buf)                                                         \
    {                                                                         \
        _Pragma("unroll")                                                     \
        for (int i = 0; i < 4; ++i) {                                         \
            int m = i * 32 + cm;                                              \
            int off = (buf) * 2048 + m * 16 + ((cc2 ^ (m & 3)) << 2);         \
            uint4 ua; ua.x = f2tf(ra[i].x); ua.y = f2tf(ra[i].y);             \
            ua.z = f2tf(ra[i].z); ua.w = f2tf(ra[i].w);                       \
            uint4 ub; ub.x = f2tf(rb[i].x); ub.y = f2tf(rb[i].y);             \
            ub.z = f2tf(rb[i].z); ub.w = f2tf(rb[i].w);                       \
            *(uint4*)&As[off] = ua;                                           \
            *(uint4*)&Bs[off] = ub;                                           \
        }                                                                     \
    }

    LD_STAGE(0);
    ST_STAGE(0);
    __syncthreads();

    const int nstages = K / 16;
    for (int s = 0; s < nstages; ++s) {
        const int buf = s & 1;
        if (s + 1 < nstages) LD_STAGE((s + 1) * 16);

#pragma unroll
        for (int k8 = 0; k8 < 2; ++k8) {
            unsigned af[4][4], bf[8][2];
#pragma unroll
            for (int mt = 0; mt < 4; ++mt) {
                int r1 = wm + mt * 16 + fr;
                int r2 = r1 + 8;
                af[mt][0] = As[buf*2048 + r1*16 + (((k8*2+0) ^ (r1&3)) << 2) + fc];
                af[mt][1] = As[buf*2048 + r2*16 + (((k8*2+0) ^ (r2&3)) << 2) + fc];
                af[mt][2] = As[buf*2048 + r1*16 + (((k8*2+1) ^ (r1&3)) << 2) + fc];
                af[mt][3] = As[buf*2048 + r2*16 + (((k8*2+1) ^ (r2&3)) << 2) + fc];
            }
#pragma unroll
            for (int nt = 0; nt < 8; ++nt) {
                int n = wn + nt * 8 + fr;
                bf[nt][0] = Bs[buf*2048 + n*16 + (((k8*2+0) ^ (n&3)) << 2) + fc];
                bf[nt][1] = Bs[buf*2048 + n*16 + (((k8*2+1) ^ (n&3)) << 2) + fc];
            }
#pragma unroll
            for (int mt = 0; mt < 4; ++mt)
#pragma unroll
                for (int nt = 0; nt < 8; ++nt) {
                    asm volatile(
                        "mma.sync.aligned.m16n8k8.row.col.f32.tf32.tf32.f32 "
                        "{%0,%1,%2,%3}, {%4,%5,%6,%7}, {%8,%9}, {%0,%1,%2,%3};"
                        : "+f"(acc[mt][nt][0]), "+f"(acc[mt][nt][1]),
                          "+f"(acc[mt][nt][2]), "+f"(acc[mt][nt][3])
                        : "r"(af[mt][0]), "r"(af[mt][1]),
                          "r"(af[mt][2]), "r"(af[mt][3]),
                          "r"(bf[nt][0]), "r"(bf[nt][1]));
                }
        }
        if (s + 1 < nstages) ST_STAGE(buf ^ 1);
        __syncthreads();
    }
#undef LD_STAGE
#undef ST_STAGE

#pragma unroll
    for (int mt = 0; mt < 4; ++mt) {
        int row = m0 + wm + mt * 16 + fr;
#pragma unroll
        for (int nt = 0; nt < 8; ++nt) {
            int col = n0 + wn + nt * 8 + fc * 2;
            float bv0 = bias[col], bv1 = bias[col + 1];
            float2 v0; v0.x = acc[mt][nt][0] + bv0; v0.y = acc[mt][nt][1] + bv1;
            float2 v1; v1.x = acc[mt][nt][2] + bv0; v1.y = acc[mt][nt][3] + bv1;
            *(float2*)&C[(size_t)row * N + col] = v0;
            *(float2*)&C[(size_t)(row + 8) * N + col] = v1;
        }
    }
}

__global__ __launch_bounds__(128) void gemm_tf32_nt_bias3(
    const float* __restrict__ A,
    const float* __restrict__ W0, const float* __restrict__ W1, const float* __restrict__ W2,
    const float* __restrict__ b0, const float* __restrict__ b1, const float* __restrict__ b2,
    float* __restrict__ C0, float* __restrict__ C1, float* __restrict__ C2,
    int M, int N, int K)
{
    __shared__ unsigned As[2 * 2048];
    __shared__ unsigned Bs[2 * 2048];
    const float* W    = (blockIdx.z == 0) ? W0 : (blockIdx.z == 1) ? W1 : W2;
    const float* bias = (blockIdx.z == 0) ? b0 : (blockIdx.z == 1) ? b1 : b2;
    float* C          = (blockIdx.z == 0) ? C0 : (blockIdx.z == 1) ? C1 : C2;
    gemm_tf32_body(As, Bs, A, W, bias, C, M, N, K);
}

// -------- logits GEMM v2: 128x256 tile, BK=32, cp.async, 8 warps ---------
// Inputs PRE-ROUNDED to tf32 (rne). 256 thr = 8 warps of 64x64.
// ~190 regs -> 8 warps/SM = 2 warps/SMSP; copy(s+1) overlaps compute(s).
__device__ __forceinline__ unsigned smem_addr_u32(const void* p)
{
    unsigned a;
    asm("{ .reg .u64 t; cvta.to.shared.u64 t, %1; cvt.u32.u64 %0, t; }"
        : "=r"(a) : "l"(p));
    return a;
}

__global__ __launch_bounds__(256) void gemm_tf32_logits(
    const float* __restrict__ A,    // [SB,512]  tf32-rounded
    const float* __restrict__ W,    // [VV,512]  tf32-rounded
    const float* __restrict__ bias,
    float* __restrict__ C)          // [SB,VV]
{
    extern __shared__ unsigned smx[];
    unsigned* As = smx;               // [2][128*32]
    unsigned* Bs = smx + 2 * 4096;    // [2][256*32]

    const int tid  = threadIdx.x;
    const int lane = tid & 31;
    const int warp = tid >> 5;        // 0..7
    const int wm = (warp >> 2) * 64;  // 2 m-warp rows
    const int wn = (warp & 3) * 64;   // 4 n-warp cols
    const int m0 = blockIdx.y * 128;
    const int n0 = blockIdx.x * 256;
    const int fr = lane >> 2;
    const int fc = lane & 3;

    float acc[4][8][4];
#pragma unroll
    for (int mt = 0; mt < 4; ++mt)
#pragma unroll
        for (int nt = 0; nt < 8; ++nt)
#pragma unroll
            for (int q = 0; q < 4; ++q) acc[mt][nt][q] = 0.f;

#define CP_STAGE(buf, k0)                                                     \
    {                                                                         \
        _Pragma("unroll")                                                     \
        for (int it = 0; it < 4; ++it) {                                      \
            int c = tid + it * 256;                                           \
            int r = c >> 3, ch = c & 7;                                       \
            unsigned d = smem_addr_u32(                                       \
                &As[(buf) * 4096 + r * 32 + ((ch ^ (r & 7)) << 2)]);          \
            const float* sp = A + (size_t)(m0 + r) * 512 + (k0) + ch * 4;     \
            asm volatile("cp.async.cg.shared.global [%0], [%1], 16;"          \
                         :: "r"(d), "l"(sp));                                 \
        }                                                                     \
        _Pragma("unroll")                                                     \
        for (int it = 0; it < 8; ++it) {                                      \
            int c = tid + it * 256;                                           \
            int r = c >> 3, ch = c & 7;                                       \
            unsigned d = smem_addr_u32(                                       \
                &Bs[(buf) * 8192 + r * 32 + ((ch ^ (r & 7)) << 2)]);          \
            const float* sp = W + (size_t)(n0 + r) * 512 + (k0) + ch * 4;     \
            asm volatile("cp.async.cg.shared.global [%0], [%1], 16;"          \
                         :: "r"(d), "l"(sp));                                 \
        }                                                                     \
        asm volatile("cp.async.commit_group;");                               \
    }

    CP_STAGE(0, 0)
    asm volatile("cp.async.wait_group 0;");
    __syncthreads();

    const int nstages = 512 / 32;    // 16
    for (int s = 0; s < nstages; ++s) {
        const int buf = s & 1;
        if (s + 1 < nstages) CP_STAGE(buf ^ 1, (s + 1) * 32)

#pragma unroll
        for (int k8 = 0; k8 < 4; ++k8) {
            const int ch0 = k8 * 2, ch1 = k8 * 2 + 1;
            unsigned af[4][4], bf[8][2];
#pragma unroll
            for (int mt = 0; mt < 4; ++mt) {
                int r1 = wm + mt * 16 + fr;
                int r2 = r1 + 8;
                af[mt][0] = As[buf*4096 + r1*32 + ((ch0 ^ (r1&7)) << 2) + fc];
                af[mt][1] = As[buf*4096 + r2*32 + ((ch0 ^ (r2&7)) << 2) + fc];
                af[mt][2] = As[buf*4096 + r1*32 + ((ch1 ^ (r1&7)) << 2) + fc];
                af[mt][3] = As[buf*4096 + r2*32 + ((ch1 ^ (r2&7)) << 2) + fc];
            }
#pragma unroll
            for (int nt = 0; nt < 8; ++nt) {
                int n = wn + nt * 8 + fr;
                bf[nt][0] = Bs[buf*8192 + n*32 + ((ch0 ^ (n&7)) << 2) + fc];
                bf[nt][1] = Bs[buf*8192 + n*32 + ((ch1 ^ (n&7)) << 2) + fc];
            }
#pragma unroll
            for (int mt = 0; mt < 4; ++mt)
#pragma unroll
                for (int nt = 0; nt < 8; ++nt) {
                    asm volatile(
                        "mma.sync.aligned.m16n8k8.row.col.f32.tf32.tf32.f32 "
                        "{%0,%1,%2,%3}, {%4,%5,%6,%7}, {%8,%9}, {%0,%1,%2,%3};"
                        : "+f"(acc[mt][nt][0]), "+f"(acc[mt][nt][1]),
                          "+f"(acc[mt][nt][2]), "+f"(acc[mt][nt][3])
                        : "r"(af[mt][0]), "r"(af[mt][1]),
                          "r"(af[mt][2]), "r"(af[mt][3]),
                          "r"(bf[nt][0]), "r"(bf[nt][1]));
                }
        }
        asm volatile("cp.async.wait_group 0;");
        __syncthreads();
    }
#undef CP_STAGE

#pragma unroll
    for (int mt = 0; mt < 4; ++mt) {
        int row = m0 + wm + mt * 16 + fr;
#pragma unroll
        for (int nt = 0; nt < 8; ++nt) {
            int col = n0 + wn + nt * 8 + fc * 2;
            float bv0 = bias[col], bv1 = bias[col + 1];
            float2 v0; v0.x = acc[mt][nt][0] + bv0; v0.y = acc[mt][nt][1] + bv1;
            float2 v1; v1.x = acc[mt][nt][2] + bv0; v1.y = acc[mt][nt][3] + bv1;
            *(float2*)&C[(size_t)row * VV + col] = v0;
            *(float2*)&C[(size_t)(row + 8) * VV + col] = v1;
        }
    }
}

// ------------- persistent GRU scan v9 (R13 winner, unchanged) ------------
__device__ __forceinline__ void fma2(unsigned long long& a,
                                     unsigned long long x, unsigned long long h)
{
    asm("fma.rn.f32x2 %0, %1, %2, %0;" : "+l"(a) : "l"(x), "l"(h));
}

__global__ __launch_bounds__(512, 1) void gru_scan_kernel(
    const float* __restrict__ gates,   // [3][SB][HH]
    const float* __restrict__ Wr,
    const float* __restrict__ Wz,
    const float* __restrict__ Wh,
    const float* __restrict__ h0,      // [BB][HH]
    float* __restrict__ hs_out,        // [SS][BB][HH]
    float* __restrict__ hfin)          // [BB][HH] or null
{
    extern __shared__ float sm[];
    float* hsm = sm;                       // [8][HSTRIDE]
    float* red = sm + 8 * HSTRIDE;         // [16][24][33]
    unsigned* sF0 = (unsigned*)(red + 16 * 24 * 33);

    const int tid  = threadIdx.x;
    const int lane = tid & 31;
    const int w    = tid >> 5;             // 0..15 = jl
    const int bid  = blockIdx.x;
    const int jg   = bid >> 2;             // 0..31
    const int bg   = bid & 3;              // 0..3
    const int j    = jg * 16 + w;

    unsigned* flags = &g_flag[bg].v[0];

    if (tid == 0) sF0[0] = flags[jg];

    ulonglong2 wv[3][4];
    {
        const float* W0 = Wr + (size_t)j * HH;
        const float* W1 = Wz + (size_t)j * HH;
        const float* W2 = Wh + (size_t)j * HH;
#pragma unroll
        for (int i = 0; i < 4; ++i) {
            int kof = 4 * lane + 128 * i;
            wv[0][i] = *(const ulonglong2*)&W0[kof];
            wv[1][i] = *(const ulonglong2*)&W1[kof];
            wv[2][i] = *(const ulonglong2*)&W2[kof];
        }
    }
    __syncthreads();
    const unsigned F0 = sF0[0];

    const int b = bg * 8 + (lane & 7);

    float xr = 0.f, xz = 0.f, xh = 0.f;
    if (lane < 8) {
        size_t idx = (size_t)(0 * BB + b) * HH + j;
        xr = __ldcg(&gates[idx]);
        xz = __ldcg(&gates[(size_t)SB * HH + idx]);
        xh = __ldcg(&gates[(size_t)2 * SB * HH + idx]);
    }

    for (int s = 0; s < SS; ++s) {
        const float* hsrc = (s == 0) ? h0 : hs_out + (size_t)(s - 1) * BB * HH;
        float* hdst = hs_out + (size_t)s * BB * HH;

        if (s > 0) {
            if (w == 0) {
                const unsigned target = F0 + (unsigned)s;
                unsigned v;
                bool ok;
                do {
                    asm volatile("ld.acquire.gpu.u32 %0, [%1];"
                                 : "=r"(v) : "l"(flags + lane) : "memory");
                    ok = __all_sync(0xffffffffu, (int)(v - target) >= 0);
                } while (!ok);
            }
            __syncthreads();
        }

#pragma unroll
        for (int it = 0; it < 2; ++it) {
            int c = tid + it * 512;
            int bs = c >> 7;
            int kq = c & 127;
            unsigned dst = (unsigned)__cvta_generic_to_shared(
                &hsm[bs * HSTRIDE + kq * 4]);
            const float* src = hsrc + (size_t)(bg * 8 + bs) * HH + kq * 4;
            asm volatile("cp.async.cg.shared.global [%0], [%1], 16;"
                         :: "r"(dst), "l"(src));
        }
        asm volatile("cp.async.commit_group;");
        asm volatile("cp.async.wait_group 0;");
        __syncthreads();

        unsigned long long acc[3][8];
#pragma unroll
        for (int g = 0; g < 3; ++g)
#pragma unroll
            for (int c = 0; c < 8; ++c) acc[g][c] = 0ULL;

#pragma unroll
        for (int i = 0; i < 4; ++i) {
            const int kof = 4 * lane + 128 * i;
#pragma unroll
            for (int c = 0; c < 8; ++c) {
                ulonglong2 hv = *(const ulonglong2*)&hsm[c * HSTRIDE + kof];
                fma2(acc[0][c], wv[0][i].x, hv.x);
                fma2(acc[0][c], wv[0][i].y, hv.y);
                fma2(acc[1][c], wv[1][i].x, hv.x);
                fma2(acc[1][c], wv[1][i].y, hv.y);
                fma2(acc[2][c], wv[2][i].x, hv.x);
                fma2(acc[2][c], wv[2][i].y, hv.y);
            }
        }

#pragma unroll
        for (int g = 0; g < 3; ++g)
#pragma unroll
            for (int c = 0; c < 8; ++c) {
                float2 f = *(float2*)&acc[g][c];
                red[(w * 24 + g * 8 + c) * 33 + lane] = f.x + f.y;
            }
        __syncwarp();

        float sum = 0.f;
        if (lane < 24) {
            int base = (w * 24 + lane) * 33;
#pragma unroll
            for (int i = 0; i < 32; ++i) sum += red[base + i];
        }
        float s0 = __shfl_sync(0xffffffffu, sum, (lane & 7));
        float s1 = __shfl_sync(0xffffffffu, sum, 8 + (lane & 7));
        float s2 = __shfl_sync(0xffffffffu, sum, 16 + (lane & 7));

        if (lane < 8) {
            float hold = hsm[(lane & 7) * HSTRIDE + j];
            float r  = 1.f / (1.f + __expf(-(xr + s0)));
            float z  = 1.f / (1.f + __expf(-(xz + s1)));
            float hc = tanhf(xh + r * s2);
            float hn = (1.f - z) * hc + z * hold;
            hdst[(size_t)b * HH + j] = hn;
            if (s == SS - 1 && hfin) hfin[(size_t)b * HH + j] = hn;
        }

        if (lane < 8 && s + 1 < SS) {
            size_t idx = (size_t)((s + 1) * BB + b) * HH + j;
            xr = __ldcg(&gates[idx]);
            xz = __ldcg(&gates[(size_t)SB * HH + idx]);
            xh = __ldcg(&gates[(size_t)2 * SB * HH + idx]);
        }

        __syncthreads();
        if (tid == 0) {
            asm volatile("st.release.gpu.u32 [%0], %1;"
                         :: "l"(flags + jg), "r"(F0 + (unsigned)s + 1u)
                         : "memory");
        }
    }
}

// ------------------------------ driver ----------------------------------
extern "C" void kernel_launch(void* const* d_in, const int* in_sizes, int n_in,
                              void* d_out, int out_size)
{
    const int*   inputs = (const int*)d_in[0];
    const float* hidden = (const float*)d_in[1];
    const float* emb    = (const float*)d_in[2];
    const float* Wir    = (const float*)d_in[3];
    const float* bir    = (const float*)d_in[4];
    const float* Wiz    = (const float*)d_in[5];
    const float* biz    = (const float*)d_in[6];
    const float* Wih    = (const float*)d_in[7];
    const float* bih    = (const float*)d_in[8];
    const float* Whr    = (const float*)d_in[9];
    const float* Whz    = (const float*)d_in[10];
    const float* Whh    = (const float*)d_in[11];
    const float* Wout   = (const float*)d_in[12];
    const float* bout   = (const float*)d_in[13];
    float* out = (float*)d_out;

    float *px, *py, *pg, *pwr;
    cudaGetSymbolAddress((void**)&px, g_x);
    cudaGetSymbolAddress((void**)&py, g_y);
    cudaGetSymbolAddress((void**)&pg, g_gates);
    cudaGetSymbolAddress((void**)&pwr, g_wr);

    const size_t logits_elems = (size_t)SB * VV;
    float* hfin_base = nullptr;
    if ((size_t)out_size >= logits_elems + (size_t)LL * BB * HH)
        hfin_base = out + logits_elems;

    const int smem_scan = (8 * HSTRIDE + 16 * 24 * 33) * sizeof(float) + 16;
    cudaFuncSetAttribute(gru_scan_kernel,
                         cudaFuncAttributeMaxDynamicSharedMemorySize, smem_scan);
    const int smem_log = (2 * 4096 + 2 * 8192) * sizeof(unsigned);  // 96KB
    cudaFuncSetAttribute(gemm_tf32_logits,
                         cudaFuncAttributeMaxDynamicSharedMemorySize, smem_log);

    // 0) profiler-window nudge (keeps -s 5 landing on the scan)
    nudge_kernel<<<1, 32>>>();

    // 1) embedding
    embed_kernel<<<SB, 128>>>(inputs, emb, px);

    const size_t CHNK = (size_t)SB * HH;
    for (int l = 0; l < LL; ++l) {
        float* in   = (l == 0) ? px : py;
        float* outb = (l == 0) ? py : px;

        // 2) fused input projections (tf32 mma, gate = blockIdx.z)
        dim3 gProj(HH / 128, SB / 128, 3);   // (4, 16, 3)
        gemm_tf32_nt_bias3<<<gProj, 128>>>(
            in,
            Wir + (size_t)l * HH * EE, Wiz + (size_t)l * HH * EE, Wih + (size_t)l * HH * EE,
            bir + l * HH, biz + l * HH, bih + l * HH,
            pg + 0 * CHNK, pg + 1 * CHNK, pg + 2 * CHNK,
            SB, HH, EE);

        // 3) persistent scan over all 64 steps (one-hop flag sync)
        gru_scan_kernel<<<NBLK, 512, smem_scan>>>(
            pg,
            Whr + (size_t)l * HH * HH,
            Whz + (size_t)l * HH * HH,
            Whh + (size_t)l * HH * HH,
            hidden + (size_t)l * BB * HH,
            outb,
            hfin_base ? hfin_base + (size_t)l * BB * HH : nullptr);
    }

    // 4) pre-round logits operands to tf32-rne
    round_tf32_kernel<<<2048, 256>>>(Wout, pwr, VV * HH / 4);
    round_tf32_kernel<<<512, 256>>>(px, px, SB * HH / 4);  // in place: sole
                                                           // consumer is logits

    // 5) logits GEMM v2 (cp.async, 128x256 tile, 8 warps)
    dim3 gLog(VV / 256, SB / 128);   // (125, 16)
    gemm_tf32_logits<<<gLog, 256, smem_log>>>(px, pwr, bout, out);
}